// round 7
// baseline (speedup 1.0000x reference)
#include <cuda_runtime.h>
#include <cuda_bf16.h>
#include <cstdint>
#include <math.h>

#define GUARD 65
#define NROW (32768 + 2 * GUARD)   // 32898

// ---------------- device scratch (no allocation allowed) ----------------
__device__ float g_tvec[64];
__device__ float g_Qt[8 * 64 * 64 * 64];
__device__ float g_Val[8 * 64 * 64 * 64];
__device__ float g_Lm[8 * 64 * 64];
// transposed mainstream, bf16 hi/lo split, XOR-swizzled rows, zero guards
__device__ __nv_bfloat16 g_m[2][NROW][128];
// B weights prepacked in mma-fragment layout:
// taps: [tap][split][kf][nf(8)][lane(32)][2] u32  (val channels only)
__device__ uint32_t g_Bt[9][2][8][8][32][2];
// center qt/key: [split][kf][nf(16)][lane][2]  (n = 64+qt / 128+key)
__device__ uint32_t g_Bq[2][8][16][32][2];

// ---------------- PTX helpers (ALL baseline sm_80-class features) -------
__device__ __forceinline__ uint32_t smem_u32(const void* p) {
    uint32_t a;
    asm("{ .reg .u64 t; cvta.to.shared.u64 t, %1; cvt.u32.u64 %0, t; }" : "=r"(a) : "l"(p));
    return a;
}
__device__ __forceinline__ void cpa16(uint32_t dst, const void* src, int bytes, int tid) {
    const char* s = (const char*)src;
    for (int o = tid * 16; o < bytes; o += 512 * 16)
        asm volatile("cp.async.cg.shared.global [%0], [%1], 16;" :: "r"(dst + o), "l"(s + o));
}
#define CP_COMMIT() asm volatile("cp.async.commit_group;" ::: "memory")
#define CP_WAIT1()  asm volatile("cp.async.wait_group 1;" ::: "memory")
#define CP_WAIT0()  asm volatile("cp.async.wait_group 0;" ::: "memory")

__device__ __forceinline__ void ldsm4(uint32_t& a0, uint32_t& a1, uint32_t& a2, uint32_t& a3,
                                      uint32_t addr) {
    asm volatile("ldmatrix.sync.aligned.m8n8.x4.shared.b16 {%0,%1,%2,%3}, [%4];"
                 : "=r"(a0), "=r"(a1), "=r"(a2), "=r"(a3) : "r"(addr));
}
__device__ __forceinline__ void lds64(uint32_t& b0, uint32_t& b1, uint32_t addr) {
    asm volatile("ld.shared.v2.u32 {%0,%1}, [%2];" : "=r"(b0), "=r"(b1) : "r"(addr));
}
__device__ __forceinline__ void mma16816(float* d, uint32_t a0, uint32_t a1, uint32_t a2,
                                         uint32_t a3, uint32_t b0, uint32_t b1) {
    asm volatile(
        "mma.sync.aligned.m16n8k16.row.col.f32.bf16.bf16.f32 "
        "{%0,%1,%2,%3}, {%4,%5,%6,%7}, {%8,%9}, {%0,%1,%2,%3};"
        : "+f"(d[0]), "+f"(d[1]), "+f"(d[2]), "+f"(d[3])
        : "r"(a0), "r"(a1), "r"(a2), "r"(a3), "r"(b0), "r"(b1));
}

__device__ __forceinline__ uint32_t pkbf(float v, float* res) {
    __nv_bfloat16 h = __float2bfloat16(v);
    *res = v - __bfloat162float(h);
    return (uint32_t)__bfloat16_as_ushort(h);
}

// ---------------------------------------------------------------------------
// k_weights: prepack B fragments (bf16 hi/lo) + tvec. 89 blocks x 256.
// ---------------------------------------------------------------------------
__global__ __launch_bounds__(256) void k_weights(const float* __restrict__ Wc,
                                                 const float* __restrict__ Wf,
                                                 const float* __restrict__ bf,
                                                 const float* __restrict__ Wk,
                                                 const float* __restrict__ Vw) {
    int T = blockIdx.x * 256 + threadIdx.x;
    if (T < 18432) {                       // val taps
        int tap = T / 2048;
        int rem = T & 2047;
        int kf = rem >> 8, nf = (rem >> 5) & 7, l = rem & 31;
        int c = nf * 8 + (l >> 2);
        int ks = kf * 16 + (l & 3) * 2;
        int fj[4] = {ks, ks + 1, ks + 8, ks + 9};
        uint32_t hb[4]; float lo[4];
#pragma unroll
        for (int j = 0; j < 4; j++)
            hb[j] = pkbf(Vw[(c * 128 + fj[j]) * 9 + tap], &lo[j]);
        g_Bt[tap][0][kf][nf][l][0] = hb[0] | (hb[1] << 16);
        g_Bt[tap][0][kf][nf][l][1] = hb[2] | (hb[3] << 16);
        uint32_t lb[4]; float dum;
#pragma unroll
        for (int j = 0; j < 4; j++) lb[j] = pkbf(lo[j], &dum);
        g_Bt[tap][1][kf][nf][l][0] = lb[0] | (lb[1] << 16);
        g_Bt[tap][1][kf][nf][l][1] = lb[2] | (lb[3] << 16);
    } else if (T < 22528) {                // center qt/key
        int T2 = T - 18432;
        int kf = T2 >> 9, nf = (T2 >> 5) & 15, l = T2 & 31;
        int n = nf * 8 + (l >> 2);
        int ks = kf * 16 + (l & 3) * 2;
        int fj[4] = {ks, ks + 1, ks + 8, ks + 9};
        uint32_t hb[4], lb[4]; float lo[4], dum;
#pragma unroll
        for (int j = 0; j < 4; j++) {
            float v;
            if (n < 64) {                  // qt: A[n][f] = Wc^T Wf
                v = 0.f;
                for (int d = 0; d < 64; d++) v = fmaf(Wc[d * 64 + n], Wf[d * 128 + fj[j]], v);
            } else {
                v = Wk[(n - 64) * 128 + fj[j]];
            }
            hb[j] = pkbf(v, &lo[j]);
            lb[j] = pkbf(lo[j], &dum);
        }
        g_Bq[0][kf][nf][l][0] = hb[0] | (hb[1] << 16);
        g_Bq[0][kf][nf][l][1] = hb[2] | (hb[3] << 16);
        g_Bq[1][kf][nf][l][0] = lb[0] | (lb[1] << 16);
        g_Bq[1][kf][nf][l][1] = lb[2] | (lb[3] << 16);
    } else if (T < 22592) {                // tvec
        int c = T - 22528;
        float t = 0.f;
        for (int d = 0; d < 64; d++) t = fmaf(Wc[d * 64 + c], bf[d], t);
        g_tvec[c] = t;
    }
}

// ---------------------------------------------------------------------------
// k_transpose: ms[B,128,64,64] -> g_m[split][65+pixel][128f], swizzled + guards
// ---------------------------------------------------------------------------
__global__ __launch_bounds__(256) void k_transpose(const float* __restrict__ ms) {
    int blk = blockIdx.x, tid = threadIdx.x;
    if (blk < 512) {
        __shared__ float sf[128 * 64];    // [f][x]
        int b = blk >> 6, y = blk & 63;
        for (int i = tid; i < 8192; i += 256)
            sf[i] = ms[((size_t)(b * 128 + (i >> 6)) * 64 + y) * 64 + (i & 63)];
        __syncthreads();
        for (int i = tid; i < 2048; i += 256) {
            int x = i & 63, ch = (i >> 6) & 15, s = i >> 10;
            int gr = GUARD + b * 4096 + y * 64 + x;
            uint32_t out[4];
#pragma unroll
            for (int ff = 0; ff < 8; ff++) {
                float v = sf[(ch * 8 + ff) * 64 + x];
                __nv_bfloat16 hv = __float2bfloat16(v);
                float val = s ? (v - __bfloat162float(hv)) : v;
                uint32_t bits = (uint32_t)__bfloat16_as_ushort(__float2bfloat16(val));
                if (ff & 1) out[ff >> 1] = (bits << 16) | (out[ff >> 1] & 0xFFFF);
                else out[ff >> 1] = bits;
            }
            int swc = ch ^ (gr & 7);
            *(uint4*)&g_m[s][gr][swc * 8] = *(uint4*)out;
        }
    } else {
        uint4 z = make_uint4(0, 0, 0, 0);
        int idx = (blk - 512) * 256 + tid;
        for (int i = idx; i < 4160; i += 1024) {
            int ch = i & 15;
            int r = (i >> 4) % 130;
            int s = i / 2080;
            int gr = (r < GUARD) ? r : (GUARD + 32768 + (r - GUARD));
            *(uint4*)&g_m[s][gr][ch * 8] = z;
        }
    }
}

// ---------------------------------------------------------------------------
// k1: mma.sync implicit GEMM. 256 blocks x 512 threads, 128 pixels/block.
// ---------------------------------------------------------------------------
#define AS_OFF 0
#define B0_OFF 67584
#define B1_OFF 100352
#define QS_OFF 133120
#define SV_OFF 0
#define SQ_OFF 33792
#define SK_OFF 67584
#define SB_OFF 198656
#define SMEM_K1 199424

__global__ __launch_bounds__(512, 1) void k1_mma(const float* __restrict__ Vb,
                                                 const float* __restrict__ bk) {
    extern __shared__ char smc[];
    uint32_t sb = smem_u32(smc);
    float* smf = (float*)smc;

    const int tid = threadIdx.x;
    const int lane = tid & 31, w = tid >> 5;
    const int mf = w & 7, nh = w >> 3;
    const int p0 = blockIdx.x * 128;
    const int lr = (lane & 7) + (lane & 8);
    const int chi = lane >> 4;

    // stage biases (region untouched by async copies)
    if (tid < 64) {
        smf[SB_OFF / 4 + tid] = bk[tid];
        smf[SB_OFF / 4 + 64 + tid] = g_tvec[tid];
        smf[SB_OFF / 4 + 128 + tid] = Vb[tid];
    }

    // initial async loads: A(hi) slab + Q, then B tap0
    cpa16(sb + AS_OFF, &g_m[0][p0][0], 66048, tid);
    cpa16(sb + QS_OFF, &g_Bq[0][0][0][0][0], 65536, tid);
    CP_COMMIT();
    cpa16(sb + B0_OFF, &g_Bt[0][0][0][0][0][0], 32768, tid);
    CP_COMMIT();

    float aV[4][4], aQ[8][4];
#pragma unroll
    for (int j = 0; j < 4; j++)
#pragma unroll
        for (int u = 0; u < 4; u++) aV[j][u] = 0.f;
#pragma unroll
    for (int j = 0; j < 8; j++)
#pragma unroll
        for (int u = 0; u < 4; u++) aQ[j][u] = 0.f;

#pragma unroll 1
    for (int phase = 0; phase < 2; phase++) {
#pragma unroll 1
        for (int t = 0; t < 9; t++) {
            uint32_t bbuf = (t & 1) ? B1_OFF : B0_OFF;
            uint32_t nbuf = (t & 1) ? B0_OFF : B1_OFF;
            if (t < 8) {
                if (phase == 0)
                    cpa16(sb + nbuf, &g_Bt[t + 1][0][0][0][0][0], 32768, tid);
                else
                    cpa16(sb + nbuf, &g_Bt[t + 1][0][0][0][0][0], 16384, tid);
                CP_COMMIT();
                CP_WAIT1();
            } else {
                CP_WAIT0();
            }
            __syncthreads();

            int dy = t / 3;
            int off = (dy - 1) * 64 + (t - dy * 3 - 1);
            int rowb = 65 + mf * 16 + off + lr;
            uint32_t abase = sb + AS_OFF + rowb * 256;
            int rph = rowb & 7;
            int passes = phase ? 1 : 2;
#pragma unroll 1
            for (int sB = 0; sB < passes; sB++) {
                uint32_t Bb = sb + bbuf + sB * 16384;
                uint32_t Qb = sb + QS_OFF + sB * 32768;   // FIXED: g_Bq split stride
#pragma unroll
                for (int kf = 0; kf < 8; kf++) {
                    uint32_t a0, a1, a2, a3;
                    ldsm4(a0, a1, a2, a3, abase + ((((kf << 1) + chi) ^ rph) << 4));
#pragma unroll
                    for (int j = 0; j < 4; j++) {
                        int nf = nh * 4 + j;
                        uint32_t b0, b1;
                        lds64(b0, b1, Bb + ((kf * 8 + nf) * 32 + lane) * 8);
                        mma16816(aV[j], a0, a1, a2, a3, b0, b1);
                    }
                    if (t == 4) {
#pragma unroll
                        for (int j = 0; j < 8; j++) {
                            int qf = nh * 8 + j;
                            uint32_t b0, b1;
                            lds64(b0, b1, Qb + ((kf * 16 + qf) * 32 + lane) * 8);
                            mma16816(aQ[j], a0, a1, a2, a3, b0, b1);
                        }
                    }
                }
            }
            __syncthreads();
        }
        if (phase == 0) {
            cpa16(sb + AS_OFF, &g_m[1][p0][0], 66048, tid);   // A lo slab
            cpa16(sb + B0_OFF, &g_Bt[0][0][0][0][0][0], 16384, tid);
            CP_COMMIT();
        }
    }

    // ---- epilogue: stage D to smem (overlay), then coalesced writeout ----
    const int r0 = mf * 16 + (lane >> 2);
#pragma unroll
    for (int j = 0; j < 4; j++) {
        int c0 = (nh * 4 + j) * 8 + (lane & 3) * 2;
        smf[SV_OFF / 4 + c0 * 132 + r0] = aV[j][0];
        smf[SV_OFF / 4 + (c0 + 1) * 132 + r0] = aV[j][1];
        smf[SV_OFF / 4 + c0 * 132 + r0 + 8] = aV[j][2];
        smf[SV_OFF / 4 + (c0 + 1) * 132 + r0 + 8] = aV[j][3];
    }
#pragma unroll
    for (int j = 0; j < 8; j++) {
        int nq = (nh * 8 + j) * 8 + (lane & 3) * 2;    // 0..63 qt | 64..127 key
        int base = (nq < 64) ? SQ_OFF / 4 : SK_OFF / 4;
        int cc = nq & 63;
        smf[base + cc * 132 + r0] = aQ[j][0];
        smf[base + (cc + 1) * 132 + r0] = aQ[j][1];
        smf[base + cc * 132 + r0 + 8] = aQ[j][2];
        smf[base + (cc + 1) * 132 + r0 + 8] = aQ[j][3];
    }
    __syncthreads();

#pragma unroll
    for (int rep = 0; rep < 16; rep++) {
        int idx = rep * 512 + tid;
        int c = idx >> 7, px = idx & 127;
        int p = p0 + px;
        int gi = ((p >> 12) * 64 + c) * 4096 + (p & 4095);
        g_Val[gi] = smf[SV_OFF / 4 + c * 132 + px] + smf[SB_OFF / 4 + 128 + c];
        g_Qt[gi] = smf[SQ_OFF / 4 + c * 132 + px] + smf[SB_OFF / 4 + 64 + c];
    }
    {
        int px = tid >> 2, q = tid & 3;
        float s = 0.f;
#pragma unroll 4
        for (int cc = q * 16; cc < q * 16 + 16; cc++) {
            float key = smf[SK_OFF / 4 + cc * 132 + px] + smf[SB_OFF / 4 + cc];
            float qt = smf[SQ_OFF / 4 + cc * 132 + px] + smf[SB_OFF / 4 + 64 + cc];
            s = fmaf(key, qt, s);
        }
        s += __shfl_down_sync(0xffffffffu, s, 1);
        s += __shfl_down_sync(0xffffffffu, s, 2);
        if (q == 0) {
            int p = p0 + px;
            g_Lm[(p >> 12) * 4096 + (p & 4095)] = s;
        }
    }
}

// ---------------------------------------------------------------------------
// k_fix: exact fp32 conv recompute on the border ring (val only). 64 blocks.
// ---------------------------------------------------------------------------
__global__ __launch_bounds__(512) void k_fix(const float* __restrict__ ms,
                                             const float* __restrict__ Vw,
                                             const float* __restrict__ Vb) {
    __shared__ float swin[3][34][8];
    int blk = blockIdx.x, tid = threadIdx.x;
    int b = blk >> 3, strip = (blk >> 1) & 3, half = blk & 1;
    bool isRow = strip < 2;
    int fixed = (strip & 1) ? 63 : 0;
    int c = tid & 63, pxg = tid >> 6;

    float acc[4] = {0.f, 0.f, 0.f, 0.f};
#pragma unroll 1
    for (int chunk = 0; chunk < 16; chunk++) {
        int f0 = chunk * 8;
        __syncthreads();
        for (int i = tid; i < 816; i += 512) {
            int t = i / 272, rr = i % 272;
            int s = rr >> 3, ff = rr & 7;
            int along = half * 32 + s - 1;
            int perp = fixed + t - 1;
            int yy = isRow ? perp : along;
            int xx = isRow ? along : perp;
            float v = 0.f;
            if (yy >= 0 && yy < 64 && xx >= 0 && xx < 64)
                v = ms[((size_t)(b * 128 + f0 + ff) * 64 + yy) * 64 + xx];
            swin[t][s][ff] = v;
        }
        __syncthreads();
#pragma unroll
        for (int ff = 0; ff < 8; ff++) {
            int f = f0 + ff;
            float wv[9];
#pragma unroll
            for (int j = 0; j < 9; j++) wv[j] = Vw[(c * 128 + f) * 9 + j];
#pragma unroll
            for (int u = 0; u < 4; u++) {
                int i = pxg * 4 + u;
                float s = acc[u];
#pragma unroll
                for (int ky = 0; ky < 3; ky++)
#pragma unroll
                    for (int kx = 0; kx < 3; kx++) {
                        int tdim = isRow ? ky : kx;
                        int sdim = i + (isRow ? kx : ky);
                        s = fmaf(wv[ky * 3 + kx], swin[tdim][sdim][ff], s);
                    }
                acc[u] = s;
            }
        }
    }
    float vb = Vb[c];
#pragma unroll
    for (int u = 0; u < 4; u++) {
        int i = pxg * 4 + u;
        int along = half * 32 + i;
        int y = isRow ? fixed : along;
        int x = isRow ? along : fixed;
        g_Val[((b * 64 + c) * 64 + y) * 64 + x] = acc[u] + vb;
    }
}

// ---------------------------------------------------------------------------
// k2: high-res attention (unchanged from the 310us passing version)
// ---------------------------------------------------------------------------
__global__ __launch_bounds__(256) void k2_highres(const float* __restrict__ ctx,
                                                  float* __restrict__ out) {
    int idx = blockIdx.x * 256 + threadIdx.x;
    int b = idx >> 13;
    int rem = idx & 8191;
    int hr = rem >> 6;
    int x = rem & 63;
    int y = hr >> 1;

    const float* qt = g_Qt + ((b * 64) * 64 + y) * 64 + x;
    const float2* cp2 = (const float2*)(ctx + (size_t)b * 3 * 64 * 16384 + hr * 128) + x;

    float2 l0 = make_float2(0.f, 0.f), l1 = l0, l2 = l0;
#pragma unroll 4
    for (int c = 0; c < 64; c++) {
        float q = qt[c * 4096];
        float2 a = cp2[c * 8192];
        float2 d = cp2[(64 + c) * 8192];
        float2 e = cp2[(128 + c) * 8192];
        l0.x = fmaf(a.x, q, l0.x); l0.y = fmaf(a.y, q, l0.y);
        l1.x = fmaf(d.x, q, l1.x); l1.y = fmaf(d.y, q, l1.y);
        l2.x = fmaf(e.x, q, l2.x); l2.y = fmaf(e.y, q, l2.y);
    }
    float l3 = g_Lm[(b * 64 + y) * 64 + x];

    float2 w0, w1, w2, w3;
    {
        float mx = fmaxf(fmaxf(l0.x, l1.x), fmaxf(l2.x, l3));
        float e0 = __expf(l0.x - mx), e1 = __expf(l1.x - mx);
        float e2 = __expf(l2.x - mx), e3 = __expf(l3 - mx);
        float inv = 1.f / (e0 + e1 + e2 + e3);
        w0.x = e0 * inv; w1.x = e1 * inv; w2.x = e2 * inv; w3.x = e3 * inv;
    }
    {
        float mx = fmaxf(fmaxf(l0.y, l1.y), fmaxf(l2.y, l3));
        float e0 = __expf(l0.y - mx), e1 = __expf(l1.y - mx);
        float e2 = __expf(l2.y - mx), e3 = __expf(l3 - mx);
        float inv = 1.f / (e0 + e1 + e2 + e3);
        w0.y = e0 * inv; w1.y = e1 * inv; w2.y = e2 * inv; w3.y = e3 * inv;
    }

    const float* vp = g_Val + ((b * 64) * 64 + y) * 64 + x;
    float2* op = (float2*)(out + (size_t)b * 64 * 16384 + hr * 128) + x;
#pragma unroll 4
    for (int c = 0; c < 64; c++) {
        float v = vp[c * 4096];
        float2 a = cp2[c * 8192];
        float2 d = cp2[(64 + c) * 8192];
        float2 e = cp2[(128 + c) * 8192];
        float2 o;
        o.x = w3.x * v; o.y = w3.y * v;
        o.x = fmaf(w0.x, a.x, o.x); o.y = fmaf(w0.y, a.y, o.y);
        o.x = fmaf(w1.x, d.x, o.x); o.y = fmaf(w1.y, d.y, o.y);
        o.x = fmaf(w2.x, e.x, o.x); o.y = fmaf(w2.y, e.y, o.y);
        op[c * 8192] = o;
    }
}

// ---------------------------------------------------------------------------
extern "C" void kernel_launch(void* const* d_in, const int* in_sizes, int n_in,
                              void* d_out, int out_size) {
    (void)in_sizes; (void)n_in; (void)out_size;
    const float* contexts = (const float*)d_in[0];
    const float* mainstream = (const float*)d_in[1];
    const float* Wc = (const float*)d_in[2];
    // d_in[3] = bc : cancels in softmax, unused
    const float* Wf = (const float*)d_in[4];
    const float* bf = (const float*)d_in[5];
    const float* Wk = (const float*)d_in[6];
    const float* bk = (const float*)d_in[7];
    const float* Vw = (const float*)d_in[8];
    const float* Vb = (const float*)d_in[9];
    float* out = (float*)d_out;

    cudaFuncSetAttribute(k1_mma, cudaFuncAttributeMaxDynamicSharedMemorySize, SMEM_K1);

    k_weights<<<89, 256>>>(Wc, Wf, bf, Wk, Vw);
    k_transpose<<<516, 256>>>(mainstream);
    k1_mma<<<256, 512, SMEM_K1>>>(Vb, bk);
    k_fix<<<64, 512>>>(mainstream, Vw, Vb);
    k2_highres<<<256, 256>>>(contexts, out);
}

// round 8
// speedup vs baseline: 2.2604x; 2.2604x over previous
#include <cuda_runtime.h>
#include <cuda_bf16.h>
#include <cstdint>
#include <math.h>

#define GUARD 65
#define NROW (32768 + 2 * GUARD)   // 32898

// ---------------- device scratch (no allocation allowed) ----------------
__device__ float g_tvec[64];
__device__ float g_Qt[8 * 64 * 64 * 64];
__device__ float g_Val[8 * 64 * 64 * 64];
__device__ float g_Lm[8 * 64 * 64];
// transposed mainstream, bf16 hi/lo split, XOR-swizzled rows, zero guards
__device__ __nv_bfloat16 g_m[2][NROW][128];
// B weights prepacked in mma-fragment layout:
// taps: [tap][split][kf][nf(8)][lane(32)][2] u32  (val channels only)
__device__ uint32_t g_Bt[9][2][8][8][32][2];
// center qt/key: [split][kf][nf(16)][lane][2]  (n = 64+qt / 128+key)
__device__ uint32_t g_Bq[2][8][16][32][2];

// ---------------- PTX helpers (ALL baseline sm_80-class features) -------
__device__ __forceinline__ uint32_t smem_u32(const void* p) {
    uint32_t a;
    asm("{ .reg .u64 t; cvta.to.shared.u64 t, %1; cvt.u32.u64 %0, t; }" : "=r"(a) : "l"(p));
    return a;
}
__device__ __forceinline__ void cpa16(uint32_t dst, const void* src, int bytes, int tid) {
    const char* s = (const char*)src;
    for (int o = tid * 16; o < bytes; o += 512 * 16)
        asm volatile("cp.async.cg.shared.global [%0], [%1], 16;" :: "r"(dst + o), "l"(s + o));
}
#define CP_COMMIT() asm volatile("cp.async.commit_group;" ::: "memory")
#define CP_WAIT1()  asm volatile("cp.async.wait_group 1;" ::: "memory")
#define CP_WAIT0()  asm volatile("cp.async.wait_group 0;" ::: "memory")

__device__ __forceinline__ void ldsm4(uint32_t& a0, uint32_t& a1, uint32_t& a2, uint32_t& a3,
                                      uint32_t addr) {
    asm volatile("ldmatrix.sync.aligned.m8n8.x4.shared.b16 {%0,%1,%2,%3}, [%4];"
                 : "=r"(a0), "=r"(a1), "=r"(a2), "=r"(a3) : "r"(addr));
}
__device__ __forceinline__ void lds64(uint32_t& b0, uint32_t& b1, uint32_t addr) {
    asm volatile("ld.shared.v2.u32 {%0,%1}, [%2];" : "=r"(b0), "=r"(b1) : "r"(addr));
}
__device__ __forceinline__ void mma16816(float* d, uint32_t a0, uint32_t a1, uint32_t a2,
                                         uint32_t a3, uint32_t b0, uint32_t b1) {
    asm volatile(
        "mma.sync.aligned.m16n8k16.row.col.f32.bf16.bf16.f32 "
        "{%0,%1,%2,%3}, {%4,%5,%6,%7}, {%8,%9}, {%0,%1,%2,%3};"
        : "+f"(d[0]), "+f"(d[1]), "+f"(d[2]), "+f"(d[3])
        : "r"(a0), "r"(a1), "r"(a2), "r"(a3), "r"(b0), "r"(b1));
}

__device__ __forceinline__ uint32_t pkbf(float v, float* res) {
    __nv_bfloat16 h = __float2bfloat16(v);
    *res = v - __bfloat162float(h);
    return (uint32_t)__bfloat16_as_ushort(h);
}

// ---------------------------------------------------------------------------
// k_weights: prepack B fragments (bf16 hi/lo) + tvec. 89 blocks x 256.
// ---------------------------------------------------------------------------
__global__ __launch_bounds__(256) void k_weights(const float* __restrict__ Wc,
                                                 const float* __restrict__ Wf,
                                                 const float* __restrict__ bf,
                                                 const float* __restrict__ Wk,
                                                 const float* __restrict__ Vw) {
    int T = blockIdx.x * 256 + threadIdx.x;
    if (T < 18432) {                       // val taps
        int tap = T / 2048;
        int rem = T & 2047;
        int kf = rem >> 8, nf = (rem >> 5) & 7, l = rem & 31;
        int c = nf * 8 + (l >> 2);
        int ks = kf * 16 + (l & 3) * 2;
        int fj[4] = {ks, ks + 1, ks + 8, ks + 9};
        uint32_t hb[4]; float lo[4];
#pragma unroll
        for (int j = 0; j < 4; j++)
            hb[j] = pkbf(Vw[(c * 128 + fj[j]) * 9 + tap], &lo[j]);
        g_Bt[tap][0][kf][nf][l][0] = hb[0] | (hb[1] << 16);
        g_Bt[tap][0][kf][nf][l][1] = hb[2] | (hb[3] << 16);
        uint32_t lb[4]; float dum;
#pragma unroll
        for (int j = 0; j < 4; j++) lb[j] = pkbf(lo[j], &dum);
        g_Bt[tap][1][kf][nf][l][0] = lb[0] | (lb[1] << 16);
        g_Bt[tap][1][kf][nf][l][1] = lb[2] | (lb[3] << 16);
    } else if (T < 22528) {                // center qt/key
        int T2 = T - 18432;
        int kf = T2 >> 9, nf = (T2 >> 5) & 15, l = T2 & 31;
        int n = nf * 8 + (l >> 2);
        int ks = kf * 16 + (l & 3) * 2;
        int fj[4] = {ks, ks + 1, ks + 8, ks + 9};
        uint32_t hb[4], lb[4]; float lo[4], dum;
#pragma unroll
        for (int j = 0; j < 4; j++) {
            float v;
            if (n < 64) {                  // qt: A[n][f] = Wc^T Wf
                v = 0.f;
                for (int d = 0; d < 64; d++) v = fmaf(Wc[d * 64 + n], Wf[d * 128 + fj[j]], v);
            } else {
                v = Wk[(n - 64) * 128 + fj[j]];
            }
            hb[j] = pkbf(v, &lo[j]);
            lb[j] = pkbf(lo[j], &dum);
        }
        g_Bq[0][kf][nf][l][0] = hb[0] | (hb[1] << 16);
        g_Bq[0][kf][nf][l][1] = hb[2] | (hb[3] << 16);
        g_Bq[1][kf][nf][l][0] = lb[0] | (lb[1] << 16);
        g_Bq[1][kf][nf][l][1] = lb[2] | (lb[3] << 16);
    } else if (T < 22592) {                // tvec
        int c = T - 22528;
        float t = 0.f;
        for (int d = 0; d < 64; d++) t = fmaf(Wc[d * 64 + c], bf[d], t);
        g_tvec[c] = t;
    }
}

// ---------------------------------------------------------------------------
// k_transpose: ms[B,128,64,64] -> g_m[split][65+pixel][128f], swizzled + guards
// ---------------------------------------------------------------------------
__global__ __launch_bounds__(256) void k_transpose(const float* __restrict__ ms) {
    int blk = blockIdx.x, tid = threadIdx.x;
    if (blk < 512) {
        __shared__ float sf[128 * 64];    // [f][x]
        int b = blk >> 6, y = blk & 63;
        for (int i = tid; i < 8192; i += 256)
            sf[i] = ms[((size_t)(b * 128 + (i >> 6)) * 64 + y) * 64 + (i & 63)];
        __syncthreads();
        for (int i = tid; i < 2048; i += 256) {
            int x = i & 63, ch = (i >> 6) & 15, s = i >> 10;
            int gr = GUARD + b * 4096 + y * 64 + x;
            uint32_t out[4];
#pragma unroll
            for (int ff = 0; ff < 8; ff++) {
                float v = sf[(ch * 8 + ff) * 64 + x];
                __nv_bfloat16 hv = __float2bfloat16(v);
                float val = s ? (v - __bfloat162float(hv)) : v;
                uint32_t bits = (uint32_t)__bfloat16_as_ushort(__float2bfloat16(val));
                if (ff & 1) out[ff >> 1] = (bits << 16) | (out[ff >> 1] & 0xFFFF);
                else out[ff >> 1] = bits;
            }
            int swc = ch ^ (gr & 7);
            *(uint4*)&g_m[s][gr][swc * 8] = *(uint4*)out;
        }
    } else {
        uint4 z = make_uint4(0, 0, 0, 0);
        int idx = (blk - 512) * 256 + tid;
        for (int i = idx; i < 4160; i += 1024) {
            int ch = i & 15;
            int r = (i >> 4) % 130;
            int s = i / 2080;
            int gr = (r < GUARD) ? r : (GUARD + 32768 + (r - GUARD));
            *(uint4*)&g_m[s][gr][ch * 8] = z;
        }
    }
}

// ---------------------------------------------------------------------------
// k1: mma.sync implicit GEMM. 256 blocks x 512 threads, 128 pixels/block.
// ---------------------------------------------------------------------------
#define AS_OFF 0
#define B0_OFF 67584
#define B1_OFF 100352
#define QS_OFF 133120
#define SV_OFF 0
#define SQ_OFF 33792
#define SK_OFF 67584
#define SB_OFF 198656
#define SMEM_K1 199424

__global__ __launch_bounds__(512, 1) void k1_mma(const float* __restrict__ Vb,
                                                 const float* __restrict__ bk) {
    extern __shared__ char smc[];
    uint32_t sb = smem_u32(smc);
    float* smf = (float*)smc;

    const int tid = threadIdx.x;
    const int lane = tid & 31, w = tid >> 5;
    const int mf = w & 7, nh = w >> 3;
    const int p0 = blockIdx.x * 128;
    const int lr = (lane & 7) + (lane & 8);
    const int chi = lane >> 4;

    // stage biases (region untouched by async copies)
    if (tid < 64) {
        smf[SB_OFF / 4 + tid] = bk[tid];
        smf[SB_OFF / 4 + 64 + tid] = g_tvec[tid];
        smf[SB_OFF / 4 + 128 + tid] = Vb[tid];
    }

    // initial async loads: A(hi) slab + Q, then B tap0
    cpa16(sb + AS_OFF, &g_m[0][p0][0], 66048, tid);
    cpa16(sb + QS_OFF, &g_Bq[0][0][0][0][0], 65536, tid);
    CP_COMMIT();
    cpa16(sb + B0_OFF, &g_Bt[0][0][0][0][0][0], 32768, tid);
    CP_COMMIT();

    float aV[4][4], aQ[8][4];
#pragma unroll
    for (int j = 0; j < 4; j++)
#pragma unroll
        for (int u = 0; u < 4; u++) aV[j][u] = 0.f;
#pragma unroll
    for (int j = 0; j < 8; j++)
#pragma unroll
        for (int u = 0; u < 4; u++) aQ[j][u] = 0.f;

#pragma unroll 1
    for (int phase = 0; phase < 2; phase++) {
#pragma unroll 1
        for (int t = 0; t < 9; t++) {
            uint32_t bbuf = (t & 1) ? B1_OFF : B0_OFF;
            uint32_t nbuf = (t & 1) ? B0_OFF : B1_OFF;
            if (t < 8) {
                if (phase == 0)
                    cpa16(sb + nbuf, &g_Bt[t + 1][0][0][0][0][0], 32768, tid);
                else
                    cpa16(sb + nbuf, &g_Bt[t + 1][0][0][0][0][0], 16384, tid);
                CP_COMMIT();
                CP_WAIT1();
            } else {
                CP_WAIT0();
            }
            __syncthreads();

            int dy = t / 3;
            int off = (dy - 1) * 64 + (t - dy * 3 - 1);
            int rowb = 65 + mf * 16 + off + lr;
            uint32_t abase = sb + AS_OFF + rowb * 256;
            int rph = rowb & 7;
            int passes = phase ? 1 : 2;
#pragma unroll 1
            for (int sB = 0; sB < passes; sB++) {
                uint32_t Bb = sb + bbuf + sB * 16384;
                uint32_t Qb = sb + QS_OFF + sB * 32768;   // g_Bq split stride
#pragma unroll
                for (int kf = 0; kf < 8; kf++) {
                    uint32_t a0, a1, a2, a3;
                    ldsm4(a0, a1, a2, a3, abase + ((((kf << 1) + chi) ^ rph) << 4));
#pragma unroll
                    for (int j = 0; j < 4; j++) {
                        int nf = nh * 4 + j;
                        uint32_t b0, b1;
                        lds64(b0, b1, Bb + ((kf * 8 + nf) * 32 + lane) * 8);
                        mma16816(aV[j], a0, a1, a2, a3, b0, b1);
                    }
                    if (t == 4) {
#pragma unroll
                        for (int j = 0; j < 8; j++) {
                            int qf = nh * 8 + j;
                            uint32_t b0, b1;
                            lds64(b0, b1, Qb + ((kf * 16 + qf) * 32 + lane) * 8);
                            mma16816(aQ[j], a0, a1, a2, a3, b0, b1);
                        }
                    }
                }
            }
            __syncthreads();
        }
        if (phase == 0) {
            cpa16(sb + AS_OFF, &g_m[1][p0][0], 66048, tid);   // A lo slab
            cpa16(sb + B0_OFF, &g_Bt[0][0][0][0][0][0], 16384, tid);
            CP_COMMIT();
        }
    }

    // ---- epilogue: stage D to smem (overlay), then coalesced writeout ----
    const int r0 = mf * 16 + (lane >> 2);
#pragma unroll
    for (int j = 0; j < 4; j++) {
        int c0 = (nh * 4 + j) * 8 + (lane & 3) * 2;
        smf[SV_OFF / 4 + c0 * 132 + r0] = aV[j][0];
        smf[SV_OFF / 4 + (c0 + 1) * 132 + r0] = aV[j][1];
        smf[SV_OFF / 4 + c0 * 132 + r0 + 8] = aV[j][2];
        smf[SV_OFF / 4 + (c0 + 1) * 132 + r0 + 8] = aV[j][3];
    }
#pragma unroll
    for (int j = 0; j < 8; j++) {
        int nq = (nh * 8 + j) * 8 + (lane & 3) * 2;    // 0..63 qt | 64..127 key
        int base = (nq < 64) ? SQ_OFF / 4 : SK_OFF / 4;
        int cc = nq & 63;
        smf[base + cc * 132 + r0] = aQ[j][0];
        smf[base + (cc + 1) * 132 + r0] = aQ[j][1];
        smf[base + cc * 132 + r0 + 8] = aQ[j][2];
        smf[base + (cc + 1) * 132 + r0 + 8] = aQ[j][3];
    }
    __syncthreads();

#pragma unroll
    for (int rep = 0; rep < 16; rep++) {
        int idx = rep * 512 + tid;
        int c = idx >> 7, px = idx & 127;
        int p = p0 + px;
        int gi = ((p >> 12) * 64 + c) * 4096 + (p & 4095);
        g_Val[gi] = smf[SV_OFF / 4 + c * 132 + px] + smf[SB_OFF / 4 + 128 + c];
        g_Qt[gi] = smf[SQ_OFF / 4 + c * 132 + px] + smf[SB_OFF / 4 + 64 + c];
    }
    {
        int px = tid >> 2, q = tid & 3;
        float s = 0.f;
#pragma unroll 4
        for (int cc = q * 16; cc < q * 16 + 16; cc++) {
            float key = smf[SK_OFF / 4 + cc * 132 + px] + smf[SB_OFF / 4 + cc];
            float qt = smf[SQ_OFF / 4 + cc * 132 + px] + smf[SB_OFF / 4 + 64 + cc];
            s = fmaf(key, qt, s);
        }
        s += __shfl_down_sync(0xffffffffu, s, 1);
        s += __shfl_down_sync(0xffffffffu, s, 2);
        if (q == 0) {
            int p = p0 + px;
            g_Lm[(p >> 12) * 4096 + (p & 4095)] = s;
        }
    }
}

// ---------------------------------------------------------------------------
// k_fix v2: exact fp32 conv recompute on the border ring.
// 128 blocks (8b x 4 strips x 4 segs of 16px), 256 threads = 64c x 4 pgroups.
// Vw staged coalesced into SMEM per f-chunk; window broadcast from SMEM.
// ---------------------------------------------------------------------------
__global__ __launch_bounds__(256) void k_fix(const float* __restrict__ ms,
                                             const float* __restrict__ Vw,
                                             const float* __restrict__ Vb) {
    __shared__ float sWv[8 * 64 * 9];      // [ff][c][9] = 4608 floats
    __shared__ float swin[3][18][8];       // [perp][along+halo][ff]
    int blk = blockIdx.x, tid = threadIdx.x;
    int b = blk >> 4, strip = (blk >> 2) & 3, seg = blk & 3;
    bool isRow = strip < 2;
    int fixed = (strip & 1) ? 63 : 0;
    int c = tid & 63, pg = tid >> 6;

    float acc[4] = {0.f, 0.f, 0.f, 0.f};
#pragma unroll 1
    for (int chunk = 0; chunk < 16; chunk++) {
        int f0 = chunk * 8;
        __syncthreads();
        // stage Vw chunk: 64 runs of 72 contiguous floats (coalesced)
        for (int i = tid; i < 4608; i += 256) {
            int cc = i / 72, r = i - cc * 72;
            sWv[(r / 9) * 576 + cc * 9 + (r - (r / 9) * 9)] = Vw[cc * 1152 + f0 * 9 + r];
        }
        // stage window: 16 px strip + halo, 3 perpendicular, 8 f
        for (int i = tid; i < 432; i += 256) {
            int ff = i / 54, r = i - ff * 54;
            int t = r / 18, al = r - t * 18;
            int along = seg * 16 + al - 1;
            int perp = fixed + t - 1;
            int yy = isRow ? perp : along;
            int xx = isRow ? along : perp;
            float v = 0.f;
            if (yy >= 0 && yy < 64 && xx >= 0 && xx < 64)
                v = ms[((size_t)(b * 128 + f0 + ff) * 64 + yy) * 64 + xx];
            swin[t][al][ff] = v;
        }
        __syncthreads();
#pragma unroll
        for (int ff = 0; ff < 8; ff++) {
            float wv[9];
#pragma unroll
            for (int j = 0; j < 9; j++) wv[j] = sWv[ff * 576 + c * 9 + j];
#pragma unroll
            for (int u = 0; u < 4; u++) {
                int i = pg * 4 + u;
                float s = acc[u];
#pragma unroll
                for (int ky = 0; ky < 3; ky++)
#pragma unroll
                    for (int kx = 0; kx < 3; kx++) {
                        int t = isRow ? ky : kx;
                        int sd = i + (isRow ? kx : ky);
                        s = fmaf(wv[ky * 3 + kx], swin[t][sd][ff], s);
                    }
                acc[u] = s;
            }
        }
    }
    float vb = Vb[c];
#pragma unroll
    for (int u = 0; u < 4; u++) {
        int along = seg * 16 + pg * 4 + u;
        int y = isRow ? fixed : along;
        int x = isRow ? along : fixed;
        g_Val[((b * 64 + c) * 64 + y) * 64 + x] = acc[u] + vb;
    }
}

// ---------------------------------------------------------------------------
// k2: high-res attention (unchanged from the passing version)
// ---------------------------------------------------------------------------
__global__ __launch_bounds__(256) void k2_highres(const float* __restrict__ ctx,
                                                  float* __restrict__ out) {
    int idx = blockIdx.x * 256 + threadIdx.x;
    int b = idx >> 13;
    int rem = idx & 8191;
    int hr = rem >> 6;
    int x = rem & 63;
    int y = hr >> 1;

    const float* qt = g_Qt + ((b * 64) * 64 + y) * 64 + x;
    const float2* cp2 = (const float2*)(ctx + (size_t)b * 3 * 64 * 16384 + hr * 128) + x;

    float2 l0 = make_float2(0.f, 0.f), l1 = l0, l2 = l0;
#pragma unroll 4
    for (int c = 0; c < 64; c++) {
        float q = qt[c * 4096];
        float2 a = cp2[c * 8192];
        float2 d = cp2[(64 + c) * 8192];
        float2 e = cp2[(128 + c) * 8192];
        l0.x = fmaf(a.x, q, l0.x); l0.y = fmaf(a.y, q, l0.y);
        l1.x = fmaf(d.x, q, l1.x); l1.y = fmaf(d.y, q, l1.y);
        l2.x = fmaf(e.x, q, l2.x); l2.y = fmaf(e.y, q, l2.y);
    }
    float l3 = g_Lm[(b * 64 + y) * 64 + x];

    float2 w0, w1, w2, w3;
    {
        float mx = fmaxf(fmaxf(l0.x, l1.x), fmaxf(l2.x, l3));
        float e0 = __expf(l0.x - mx), e1 = __expf(l1.x - mx);
        float e2 = __expf(l2.x - mx), e3 = __expf(l3 - mx);
        float inv = 1.f / (e0 + e1 + e2 + e3);
        w0.x = e0 * inv; w1.x = e1 * inv; w2.x = e2 * inv; w3.x = e3 * inv;
    }
    {
        float mx = fmaxf(fmaxf(l0.y, l1.y), fmaxf(l2.y, l3));
        float e0 = __expf(l0.y - mx), e1 = __expf(l1.y - mx);
        float e2 = __expf(l2.y - mx), e3 = __expf(l3 - mx);
        float inv = 1.f / (e0 + e1 + e2 + e3);
        w0.y = e0 * inv; w1.y = e1 * inv; w2.y = e2 * inv; w3.y = e3 * inv;
    }

    const float* vp = g_Val + ((b * 64) * 64 + y) * 64 + x;
    float2* op = (float2*)(out + (size_t)b * 64 * 16384 + hr * 128) + x;
#pragma unroll 4
    for (int c = 0; c < 64; c++) {
        float v = vp[c * 4096];
        float2 a = cp2[c * 8192];
        float2 d = cp2[(64 + c) * 8192];
        float2 e = cp2[(128 + c) * 8192];
        float2 o;
        o.x = w3.x * v; o.y = w3.y * v;
        o.x = fmaf(w0.x, a.x, o.x); o.y = fmaf(w0.y, a.y, o.y);
        o.x = fmaf(w1.x, d.x, o.x); o.y = fmaf(w1.y, d.y, o.y);
        o.x = fmaf(w2.x, e.x, o.x); o.y = fmaf(w2.y, e.y, o.y);
        op[c * 8192] = o;
    }
}

// ---------------------------------------------------------------------------
extern "C" void kernel_launch(void* const* d_in, const int* in_sizes, int n_in,
                              void* d_out, int out_size) {
    (void)in_sizes; (void)n_in; (void)out_size;
    const float* contexts = (const float*)d_in[0];
    const float* mainstream = (const float*)d_in[1];
    const float* Wc = (const float*)d_in[2];
    // d_in[3] = bc : cancels in softmax, unused
    const float* Wf = (const float*)d_in[4];
    const float* bf = (const float*)d_in[5];
    const float* Wk = (const float*)d_in[6];
    const float* bk = (const float*)d_in[7];
    const float* Vw = (const float*)d_in[8];
    const float* Vb = (const float*)d_in[9];
    float* out = (float*)d_out;

    cudaFuncSetAttribute(k1_mma, cudaFuncAttributeMaxDynamicSharedMemorySize, SMEM_K1);

    k_weights<<<89, 256>>>(Wc, Wf, bf, Wk, Vw);
    k_transpose<<<516, 256>>>(mainstream);
    k1_mma<<<256, 512, SMEM_K1>>>(Vb, bk);
    k_fix<<<128, 256>>>(mainstream, Vw, Vb);
    k2_highres<<<256, 256>>>(contexts, out);
}

// round 9
// speedup vs baseline: 2.3434x; 1.0367x over previous
#include <cuda_runtime.h>
#include <cuda_bf16.h>
#include <cstdint>
#include <math.h>

#define GUARD 65
#define NROW (32768 + 2 * GUARD)   // 32898

// ---------------- device scratch (no allocation allowed) ----------------
__device__ float g_tvec[64];
__device__ float g_Qt[8 * 64 * 64 * 64];
__device__ float g_Val[8 * 64 * 64 * 64];
__device__ float g_Lm[8 * 64 * 64];
// transposed mainstream, bf16 hi/lo split, XOR-swizzled rows, zero guards
__device__ __nv_bfloat16 g_m[2][NROW][128];
// B weights prepacked in mma-fragment layout:
// taps: [tap][split][kf][nf(8)][lane(32)][2] u32  (val channels only)
__device__ uint32_t g_Bt[9][2][8][8][32][2];
// center qt/key: [split][kf][nf(16)][lane][2]  (n = 64+qt / 128+key)
__device__ uint32_t g_Bq[2][8][16][32][2];

// ---------------- PTX helpers (ALL baseline sm_80-class features) -------
__device__ __forceinline__ uint32_t smem_u32(const void* p) {
    uint32_t a;
    asm("{ .reg .u64 t; cvta.to.shared.u64 t, %1; cvt.u32.u64 %0, t; }" : "=r"(a) : "l"(p));
    return a;
}
__device__ __forceinline__ void cpa16(uint32_t dst, const void* src, int bytes, int tid) {
    const char* s = (const char*)src;
    for (int o = tid * 16; o < bytes; o += 512 * 16)
        asm volatile("cp.async.cg.shared.global [%0], [%1], 16;" :: "r"(dst + o), "l"(s + o));
}
#define CP_COMMIT() asm volatile("cp.async.commit_group;" ::: "memory")
#define CP_WAIT1()  asm volatile("cp.async.wait_group 1;" ::: "memory")
#define CP_WAIT0()  asm volatile("cp.async.wait_group 0;" ::: "memory")

__device__ __forceinline__ void ldsm4(uint32_t& a0, uint32_t& a1, uint32_t& a2, uint32_t& a3,
                                      uint32_t addr) {
    asm volatile("ldmatrix.sync.aligned.m8n8.x4.shared.b16 {%0,%1,%2,%3}, [%4];"
                 : "=r"(a0), "=r"(a1), "=r"(a2), "=r"(a3) : "r"(addr));
}
__device__ __forceinline__ void lds64(uint32_t& b0, uint32_t& b1, uint32_t addr) {
    asm volatile("ld.shared.v2.u32 {%0,%1}, [%2];" : "=r"(b0), "=r"(b1) : "r"(addr));
}
__device__ __forceinline__ void mma16816(float* d, uint32_t a0, uint32_t a1, uint32_t a2,
                                         uint32_t a3, uint32_t b0, uint32_t b1) {
    asm volatile(
        "mma.sync.aligned.m16n8k16.row.col.f32.bf16.bf16.f32 "
        "{%0,%1,%2,%3}, {%4,%5,%6,%7}, {%8,%9}, {%0,%1,%2,%3};"
        : "+f"(d[0]), "+f"(d[1]), "+f"(d[2]), "+f"(d[3])
        : "r"(a0), "r"(a1), "r"(a2), "r"(a3), "r"(b0), "r"(b1));
}

__device__ __forceinline__ uint32_t pkbf(float v, float* res) {
    __nv_bfloat16 h = __float2bfloat16(v);
    *res = v - __bfloat162float(h);
    return (uint32_t)__bfloat16_as_ushort(h);
}

// ---------------------------------------------------------------------------
// k_weights: prepack B fragments (bf16 hi/lo) + tvec. 89 blocks x 256.
// ---------------------------------------------------------------------------
__global__ __launch_bounds__(256) void k_weights(const float* __restrict__ Wc,
                                                 const float* __restrict__ Wf,
                                                 const float* __restrict__ bf,
                                                 const float* __restrict__ Wk,
                                                 const float* __restrict__ Vw) {
    int T = blockIdx.x * 256 + threadIdx.x;
    if (T < 18432) {                       // val taps
        int tap = T / 2048;
        int rem = T & 2047;
        int kf = rem >> 8, nf = (rem >> 5) & 7, l = rem & 31;
        int c = nf * 8 + (l >> 2);
        int ks = kf * 16 + (l & 3) * 2;
        int fj[4] = {ks, ks + 1, ks + 8, ks + 9};
        uint32_t hb[4]; float lo[4];
#pragma unroll
        for (int j = 0; j < 4; j++)
            hb[j] = pkbf(Vw[(c * 128 + fj[j]) * 9 + tap], &lo[j]);
        g_Bt[tap][0][kf][nf][l][0] = hb[0] | (hb[1] << 16);
        g_Bt[tap][0][kf][nf][l][1] = hb[2] | (hb[3] << 16);
        uint32_t lb[4]; float dum;
#pragma unroll
        for (int j = 0; j < 4; j++) lb[j] = pkbf(lo[j], &dum);
        g_Bt[tap][1][kf][nf][l][0] = lb[0] | (lb[1] << 16);
        g_Bt[tap][1][kf][nf][l][1] = lb[2] | (lb[3] << 16);
    } else if (T < 22528) {                // center qt/key
        int T2 = T - 18432;
        int kf = T2 >> 9, nf = (T2 >> 5) & 15, l = T2 & 31;
        int n = nf * 8 + (l >> 2);
        int ks = kf * 16 + (l & 3) * 2;
        int fj[4] = {ks, ks + 1, ks + 8, ks + 9};
        uint32_t hb[4], lb[4]; float lo[4], dum;
#pragma unroll
        for (int j = 0; j < 4; j++) {
            float v;
            if (n < 64) {                  // qt: A[n][f] = Wc^T Wf
                v = 0.f;
                for (int d = 0; d < 64; d++) v = fmaf(Wc[d * 64 + n], Wf[d * 128 + fj[j]], v);
            } else {
                v = Wk[(n - 64) * 128 + fj[j]];
            }
            hb[j] = pkbf(v, &lo[j]);
            lb[j] = pkbf(lo[j], &dum);
        }
        g_Bq[0][kf][nf][l][0] = hb[0] | (hb[1] << 16);
        g_Bq[0][kf][nf][l][1] = hb[2] | (hb[3] << 16);
        g_Bq[1][kf][nf][l][0] = lb[0] | (lb[1] << 16);
        g_Bq[1][kf][nf][l][1] = lb[2] | (lb[3] << 16);
    } else if (T < 22592) {                // tvec
        int c = T - 22528;
        float t = 0.f;
        for (int d = 0; d < 64; d++) t = fmaf(Wc[d * 64 + c], bf[d], t);
        g_tvec[c] = t;
    }
}

// ---------------------------------------------------------------------------
// k_transpose: ms[B,128,64,64] -> g_m[split][65+pixel][128f], swizzled + guards
// ---------------------------------------------------------------------------
__global__ __launch_bounds__(256) void k_transpose(const float* __restrict__ ms) {
    int blk = blockIdx.x, tid = threadIdx.x;
    if (blk < 512) {
        __shared__ float sf[128 * 64];    // [f][x]
        int b = blk >> 6, y = blk & 63;
        for (int i = tid; i < 8192; i += 256)
            sf[i] = ms[((size_t)(b * 128 + (i >> 6)) * 64 + y) * 64 + (i & 63)];
        __syncthreads();
        for (int i = tid; i < 2048; i += 256) {
            int x = i & 63, ch = (i >> 6) & 15, s = i >> 10;
            int gr = GUARD + b * 4096 + y * 64 + x;
            uint32_t out[4];
#pragma unroll
            for (int ff = 0; ff < 8; ff++) {
                float v = sf[(ch * 8 + ff) * 64 + x];
                __nv_bfloat16 hv = __float2bfloat16(v);
                float val = s ? (v - __bfloat162float(hv)) : v;
                uint32_t bits = (uint32_t)__bfloat16_as_ushort(__float2bfloat16(val));
                if (ff & 1) out[ff >> 1] = (bits << 16) | (out[ff >> 1] & 0xFFFF);
                else out[ff >> 1] = bits;
            }
            int swc = ch ^ (gr & 7);
            *(uint4*)&g_m[s][gr][swc * 8] = *(uint4*)out;
        }
    } else {
        uint4 z = make_uint4(0, 0, 0, 0);
        int idx = (blk - 512) * 256 + tid;
        for (int i = idx; i < 4160; i += 1024) {
            int ch = i & 15;
            int r = (i >> 4) % 130;
            int s = i / 2080;
            int gr = (r < GUARD) ? r : (GUARD + 32768 + (r - GUARD));
            *(uint4*)&g_m[s][gr][ch * 8] = z;
        }
    }
}

// ---------------------------------------------------------------------------
// k1: mma.sync implicit GEMM. 256 blocks x 512 threads, 128 pixels/block.
// ---------------------------------------------------------------------------
#define AS_OFF 0
#define B0_OFF 67584
#define B1_OFF 100352
#define QS_OFF 133120
#define SV_OFF 0
#define SQ_OFF 33792
#define SK_OFF 67584
#define SB_OFF 198656
#define SMEM_K1 199424

__global__ __launch_bounds__(512, 1) void k1_mma(const float* __restrict__ Vb,
                                                 const float* __restrict__ bk) {
    extern __shared__ char smc[];
    uint32_t sb = smem_u32(smc);
    float* smf = (float*)smc;

    const int tid = threadIdx.x;
    const int lane = tid & 31, w = tid >> 5;
    const int mf = w & 7, nh = w >> 3;
    const int p0 = blockIdx.x * 128;
    const int lr = (lane & 7) + (lane & 8);
    const int chi = lane >> 4;

    // stage biases (region untouched by async copies)
    if (tid < 64) {
        smf[SB_OFF / 4 + tid] = bk[tid];
        smf[SB_OFF / 4 + 64 + tid] = g_tvec[tid];
        smf[SB_OFF / 4 + 128 + tid] = Vb[tid];
    }

    // initial async loads: A(hi) slab + Q, then B tap0
    cpa16(sb + AS_OFF, &g_m[0][p0][0], 66048, tid);
    cpa16(sb + QS_OFF, &g_Bq[0][0][0][0][0], 65536, tid);
    CP_COMMIT();
    cpa16(sb + B0_OFF, &g_Bt[0][0][0][0][0][0], 32768, tid);
    CP_COMMIT();

    float aV[4][4], aQ[8][4];
#pragma unroll
    for (int j = 0; j < 4; j++)
#pragma unroll
        for (int u = 0; u < 4; u++) aV[j][u] = 0.f;
#pragma unroll
    for (int j = 0; j < 8; j++)
#pragma unroll
        for (int u = 0; u < 4; u++) aQ[j][u] = 0.f;

#pragma unroll 1
    for (int phase = 0; phase < 2; phase++) {
#pragma unroll 1
        for (int t = 0; t < 9; t++) {
            uint32_t bbuf = (t & 1) ? B1_OFF : B0_OFF;
            uint32_t nbuf = (t & 1) ? B0_OFF : B1_OFF;
            if (t < 8) {
                if (phase == 0)
                    cpa16(sb + nbuf, &g_Bt[t + 1][0][0][0][0][0], 32768, tid);
                else
                    cpa16(sb + nbuf, &g_Bt[t + 1][0][0][0][0][0], 16384, tid);
                CP_COMMIT();
                CP_WAIT1();
            } else {
                CP_WAIT0();
            }
            __syncthreads();

            int dy = t / 3;
            int off = (dy - 1) * 64 + (t - dy * 3 - 1);
            int rowb = 65 + mf * 16 + off + lr;
            uint32_t abase = sb + AS_OFF + rowb * 256;
            int rph = rowb & 7;
            int passes = phase ? 1 : 2;
#pragma unroll 1
            for (int sB = 0; sB < passes; sB++) {
                uint32_t Bb = sb + bbuf + sB * 16384;
                uint32_t Qb = sb + QS_OFF + sB * 32768;   // g_Bq split stride
#pragma unroll
                for (int kf = 0; kf < 8; kf++) {
                    uint32_t a0, a1, a2, a3;
                    ldsm4(a0, a1, a2, a3, abase + ((((kf << 1) + chi) ^ rph) << 4));
#pragma unroll
                    for (int j = 0; j < 4; j++) {
                        int nf = nh * 4 + j;
                        uint32_t b0, b1;
                        lds64(b0, b1, Bb + ((kf * 8 + nf) * 32 + lane) * 8);
                        mma16816(aV[j], a0, a1, a2, a3, b0, b1);
                    }
                    if (t == 4) {
#pragma unroll
                        for (int j = 0; j < 8; j++) {
                            int qf = nh * 8 + j;
                            uint32_t b0, b1;
                            lds64(b0, b1, Qb + ((kf * 16 + qf) * 32 + lane) * 8);
                            mma16816(aQ[j], a0, a1, a2, a3, b0, b1);
                        }
                    }
                }
            }
            __syncthreads();
        }
        if (phase == 0) {
            cpa16(sb + AS_OFF, &g_m[1][p0][0], 66048, tid);   // A lo slab
            cpa16(sb + B0_OFF, &g_Bt[0][0][0][0][0][0], 16384, tid);
            CP_COMMIT();
        }
    }

    // ---- epilogue: stage D to smem (overlay), then coalesced writeout ----
    const int r0 = mf * 16 + (lane >> 2);
#pragma unroll
    for (int j = 0; j < 4; j++) {
        int c0 = (nh * 4 + j) * 8 + (lane & 3) * 2;
        smf[SV_OFF / 4 + c0 * 132 + r0] = aV[j][0];
        smf[SV_OFF / 4 + (c0 + 1) * 132 + r0] = aV[j][1];
        smf[SV_OFF / 4 + c0 * 132 + r0 + 8] = aV[j][2];
        smf[SV_OFF / 4 + (c0 + 1) * 132 + r0 + 8] = aV[j][3];
    }
#pragma unroll
    for (int j = 0; j < 8; j++) {
        int nq = (nh * 8 + j) * 8 + (lane & 3) * 2;    // 0..63 qt | 64..127 key
        int base = (nq < 64) ? SQ_OFF / 4 : SK_OFF / 4;
        int cc = nq & 63;
        smf[base + cc * 132 + r0] = aQ[j][0];
        smf[base + (cc + 1) * 132 + r0] = aQ[j][1];
        smf[base + cc * 132 + r0 + 8] = aQ[j][2];
        smf[base + (cc + 1) * 132 + r0 + 8] = aQ[j][3];
    }
    __syncthreads();

#pragma unroll
    for (int rep = 0; rep < 16; rep++) {
        int idx = rep * 512 + tid;
        int c = idx >> 7, px = idx & 127;
        int p = p0 + px;
        int gi = ((p >> 12) * 64 + c) * 4096 + (p & 4095);
        g_Val[gi] = smf[SV_OFF / 4 + c * 132 + px] + smf[SB_OFF / 4 + 128 + c];
        g_Qt[gi] = smf[SQ_OFF / 4 + c * 132 + px] + smf[SB_OFF / 4 + 64 + c];
    }
    {
        int px = tid >> 2, q = tid & 3;
        float s = 0.f;
#pragma unroll 4
        for (int cc = q * 16; cc < q * 16 + 16; cc++) {
            float key = smf[SK_OFF / 4 + cc * 132 + px] + smf[SB_OFF / 4 + cc];
            float qt = smf[SQ_OFF / 4 + cc * 132 + px] + smf[SB_OFF / 4 + 64 + cc];
            s = fmaf(key, qt, s);
        }
        s += __shfl_down_sync(0xffffffffu, s, 1);
        s += __shfl_down_sync(0xffffffffu, s, 2);
        if (q == 0) {
            int p = p0 + px;
            g_Lm[(p >> 12) * 4096 + (p & 4095)] = s;
        }
    }
}

// ---------------------------------------------------------------------------
// k_fix v3: exact fp32 conv recompute on the border ring.
// 256 blocks (8b x 4 strips x 8 segs of 8px), 256 thr = 64c x 4pg (2px each).
// 6 valid taps only; Vw+window register-prefetch pipeline hides LDG latency.
// ---------------------------------------------------------------------------
__global__ __launch_bounds__(256) void k_fix(const float* __restrict__ ms,
                                             const float* __restrict__ Vw,
                                             const float* __restrict__ Vb) {
    __shared__ float sWv[8 * 64 * 9];      // [ff][c][9] = 4608 (gcd(9,32)=1: conflict-free)
    __shared__ float swin[3 * 10 * 8];     // [perp(3)][along 8+2halo][ff]

    const int blk = blockIdx.x, tid = threadIdx.x;
    const int b = blk >> 5, strip = (blk >> 3) & 3, seg = blk & 7;
    const bool isRow = strip < 2;
    const int fixed = (strip & 1) ? 63 : 0;
    const int c = tid & 63, pg = tid >> 6;

    // build the 6 valid taps (uniform per block, unrolled -> stays in regs)
    int jl[6], pl[6], ao[6];
    {
        int q = 0;
#pragma unroll
        for (int ky = 0; ky < 3; ky++)
#pragma unroll
            for (int kx = 0; kx < 3; kx++) {
                int perp = isRow ? ky : kx;
                // invalid perp tap: strip 0/2 -> perp 0; strip 1/3 -> perp 2
                bool valid = (strip & 1) ? (perp != 2) : (perp != 0);
                if (valid) { jl[q] = ky * 3 + kx; pl[q] = perp; ao[q] = isRow ? kx : ky; q++; }
            }
    }

    // ---- prefetch chunk 0 ----
    float pf[18];
#pragma unroll
    for (int k = 0; k < 18; k++) {
        int i = tid + k * 256;
        pf[k] = Vw[(i / 72) * 1152 + (i % 72)];   // chunk 0: f0*9 = 0
    }
    float ws = 0.f;
    if (tid < 240) {
        int ff = tid / 30, rr = tid % 30;
        int t = rr / 10, al = rr % 10;
        int along = seg * 8 + al - 1;
        int perp = fixed + t - 1;
        int yy = isRow ? perp : along;
        int xx = isRow ? along : perp;
        if (yy >= 0 && yy < 64 && xx >= 0 && xx < 64)
            ws = ms[((size_t)(b * 128 + ff) * 64 + yy) * 64 + xx];
    }

    float acc[2] = {0.f, 0.f};
#pragma unroll 1
    for (int chunk = 0; chunk < 16; chunk++) {
        __syncthreads();   // previous compute done -> smem reusable
#pragma unroll
        for (int k = 0; k < 18; k++) {
            int i = tid + k * 256;
            int cc = i / 72, r = i - cc * 72;
            sWv[(r / 9) * 576 + cc * 9 + (r % 9)] = pf[k];
        }
        if (tid < 240) {
            int ff = tid / 30, rr = tid % 30;
            swin[(rr) * 8 + ff] = ws;   // [t*10+al][ff]
        }
        __syncthreads();
        // prefetch next chunk while computing this one
        if (chunk < 15) {
            int f0n = (chunk + 1) * 8;
#pragma unroll
            for (int k = 0; k < 18; k++) {
                int i = tid + k * 256;
                pf[k] = Vw[(i / 72) * 1152 + f0n * 9 + (i % 72)];
            }
            if (tid < 240) {
                int ff = tid / 30, rr = tid % 30;
                int t = rr / 10, al = rr % 10;
                int along = seg * 8 + al - 1;
                int perp = fixed + t - 1;
                int yy = isRow ? perp : along;
                int xx = isRow ? along : perp;
                ws = 0.f;
                if (yy >= 0 && yy < 64 && xx >= 0 && xx < 64)
                    ws = ms[((size_t)(b * 128 + f0n + ff) * 64 + yy) * 64 + xx];
            }
        }
        // compute: 8 ff x 6 taps x 2 px
#pragma unroll
        for (int ff = 0; ff < 8; ff++) {
            float wv[6];
#pragma unroll
            for (int q = 0; q < 6; q++) wv[q] = sWv[ff * 576 + c * 9 + jl[q]];
#pragma unroll
            for (int u = 0; u < 2; u++) {
                int i = pg * 2 + u;
                float s = acc[u];
#pragma unroll
                for (int q = 0; q < 6; q++)
                    s = fmaf(wv[q], swin[(pl[q] * 10 + i + ao[q]) * 8 + ff], s);
                acc[u] = s;
            }
        }
    }

    float vb = Vb[c];
#pragma unroll
    for (int u = 0; u < 2; u++) {
        int along = seg * 8 + pg * 2 + u;
        int y = isRow ? fixed : along;
        int x = isRow ? along : fixed;
        g_Val[((b * 64 + c) * 64 + y) * 64 + x] = acc[u] + vb;
    }
}

// ---------------------------------------------------------------------------
// k2: high-res attention (unchanged from the passing version)
// ---------------------------------------------------------------------------
__global__ __launch_bounds__(256) void k2_highres(const float* __restrict__ ctx,
                                                  float* __restrict__ out) {
    int idx = blockIdx.x * 256 + threadIdx.x;
    int b = idx >> 13;
    int rem = idx & 8191;
    int hr = rem >> 6;
    int x = rem & 63;
    int y = hr >> 1;

    const float* qt = g_Qt + ((b * 64) * 64 + y) * 64 + x;
    const float2* cp2 = (const float2*)(ctx + (size_t)b * 3 * 64 * 16384 + hr * 128) + x;

    float2 l0 = make_float2(0.f, 0.f), l1 = l0, l2 = l0;
#pragma unroll 4
    for (int c = 0; c < 64; c++) {
        float q = qt[c * 4096];
        float2 a = cp2[c * 8192];
        float2 d = cp2[(64 + c) * 8192];
        float2 e = cp2[(128 + c) * 8192];
        l0.x = fmaf(a.x, q, l0.x); l0.y = fmaf(a.y, q, l0.y);
        l1.x = fmaf(d.x, q, l1.x); l1.y = fmaf(d.y, q, l1.y);
        l2.x = fmaf(e.x, q, l2.x); l2.y = fmaf(e.y, q, l2.y);
    }
    float l3 = g_Lm[(b * 64 + y) * 64 + x];

    float2 w0, w1, w2, w3;
    {
        float mx = fmaxf(fmaxf(l0.x, l1.x), fmaxf(l2.x, l3));
        float e0 = __expf(l0.x - mx), e1 = __expf(l1.x - mx);
        float e2 = __expf(l2.x - mx), e3 = __expf(l3 - mx);
        float inv = 1.f / (e0 + e1 + e2 + e3);
        w0.x = e0 * inv; w1.x = e1 * inv; w2.x = e2 * inv; w3.x = e3 * inv;
    }
    {
        float mx = fmaxf(fmaxf(l0.y, l1.y), fmaxf(l2.y, l3));
        float e0 = __expf(l0.y - mx), e1 = __expf(l1.y - mx);
        float e2 = __expf(l2.y - mx), e3 = __expf(l3 - mx);
        float inv = 1.f / (e0 + e1 + e2 + e3);
        w0.y = e0 * inv; w1.y = e1 * inv; w2.y = e2 * inv; w3.y = e3 * inv;
    }

    const float* vp = g_Val + ((b * 64) * 64 + y) * 64 + x;
    float2* op = (float2*)(out + (size_t)b * 64 * 16384 + hr * 128) + x;
#pragma unroll 4
    for (int c = 0; c < 64; c++) {
        float v = vp[c * 4096];
        float2 a = cp2[c * 8192];
        float2 d = cp2[(64 + c) * 8192];
        float2 e = cp2[(128 + c) * 8192];
        float2 o;
        o.x = w3.x * v; o.y = w3.y * v;
        o.x = fmaf(w0.x, a.x, o.x); o.y = fmaf(w0.y, a.y, o.y);
        o.x = fmaf(w1.x, d.x, o.x); o.y = fmaf(w1.y, d.y, o.y);
        o.x = fmaf(w2.x, e.x, o.x); o.y = fmaf(w2.y, e.y, o.y);
        op[c * 8192] = o;
    }
}

// ---------------------------------------------------------------------------
extern "C" void kernel_launch(void* const* d_in, const int* in_sizes, int n_in,
                              void* d_out, int out_size) {
    (void)in_sizes; (void)n_in; (void)out_size;
    const float* contexts = (const float*)d_in[0];
    const float* mainstream = (const float*)d_in[1];
    const float* Wc = (const float*)d_in[2];
    // d_in[3] = bc : cancels in softmax, unused
    const float* Wf = (const float*)d_in[4];
    const float* bf = (const float*)d_in[5];
    const float* Wk = (const float*)d_in[6];
    const float* bk = (const float*)d_in[7];
    const float* Vw = (const float*)d_in[8];
    const float* Vb = (const float*)d_in[9];
    float* out = (float*)d_out;

    cudaFuncSetAttribute(k1_mma, cudaFuncAttributeMaxDynamicSharedMemorySize, SMEM_K1);

    k_weights<<<89, 256>>>(Wc, Wf, bf, Wk, Vw);
    k_transpose<<<516, 256>>>(mainstream);
    k1_mma<<<256, 512, SMEM_K1>>>(Vb, bk);
    k_fix<<<256, 256>>>(mainstream, Vw, Vb);
    k2_highres<<<256, 256>>>(contexts, out);
}

// round 10
// speedup vs baseline: 2.9042x; 1.2393x over previous
#include <cuda_runtime.h>
#include <cuda_bf16.h>
#include <cstdint>
#include <math.h>

// padded image: 66x66 slots per image, pixel (y,x) at slot (y+1)*66+(x+1)
#define IMG_SLOTS 4356
#define NROW (8 * IMG_SLOTS)   // 34848 padded pixel rows

// ---------------- device scratch (no allocation allowed) ----------------
__device__ float g_tvec[64];
__device__ float g_Qt[8 * 64 * 64 * 64];
__device__ float g_Val[8 * 64 * 64 * 64];
__device__ float g_Lm[8 * 64 * 64];
// transposed mainstream, bf16 hi/lo split, XOR-swizzled rows, per-image pad ring
__device__ __nv_bfloat16 g_m[2][NROW][128];
// B weights prepacked in mma-fragment layout:
// taps: [tap][split][kf][nf(8)][lane(32)][2] u32  (val channels only)
__device__ uint32_t g_Bt[9][2][8][8][32][2];
// center qt/key: [split][kf][nf(16)][lane][2]  (n = 64+qt / 128+key)
__device__ uint32_t g_Bq[2][8][16][32][2];

// ---------------- PTX helpers (ALL baseline sm_80-class features) -------
__device__ __forceinline__ uint32_t smem_u32(const void* p) {
    uint32_t a;
    asm("{ .reg .u64 t; cvta.to.shared.u64 t, %1; cvt.u32.u64 %0, t; }" : "=r"(a) : "l"(p));
    return a;
}
__device__ __forceinline__ void cpa16(uint32_t dst, const void* src, int bytes, int tid) {
    const char* s = (const char*)src;
    for (int o = tid * 16; o < bytes; o += 512 * 16)
        asm volatile("cp.async.cg.shared.global [%0], [%1], 16;" :: "r"(dst + o), "l"(s + o));
}
#define CP_COMMIT() asm volatile("cp.async.commit_group;" ::: "memory")
#define CP_WAIT1()  asm volatile("cp.async.wait_group 1;" ::: "memory")
#define CP_WAIT0()  asm volatile("cp.async.wait_group 0;" ::: "memory")

__device__ __forceinline__ void ldsm4(uint32_t& a0, uint32_t& a1, uint32_t& a2, uint32_t& a3,
                                      uint32_t addr) {
    asm volatile("ldmatrix.sync.aligned.m8n8.x4.shared.b16 {%0,%1,%2,%3}, [%4];"
                 : "=r"(a0), "=r"(a1), "=r"(a2), "=r"(a3) : "r"(addr));
}
__device__ __forceinline__ void lds64(uint32_t& b0, uint32_t& b1, uint32_t addr) {
    asm volatile("ld.shared.v2.u32 {%0,%1}, [%2];" : "=r"(b0), "=r"(b1) : "r"(addr));
}
__device__ __forceinline__ void mma16816(float* d, uint32_t a0, uint32_t a1, uint32_t a2,
                                         uint32_t a3, uint32_t b0, uint32_t b1) {
    asm volatile(
        "mma.sync.aligned.m16n8k16.row.col.f32.bf16.bf16.f32 "
        "{%0,%1,%2,%3}, {%4,%5,%6,%7}, {%8,%9}, {%0,%1,%2,%3};"
        : "+f"(d[0]), "+f"(d[1]), "+f"(d[2]), "+f"(d[3])
        : "r"(a0), "r"(a1), "r"(a2), "r"(a3), "r"(b0), "r"(b1));
}

__device__ __forceinline__ uint32_t pkbf(float v, float* res) {
    __nv_bfloat16 h = __float2bfloat16(v);
    *res = v - __bfloat162float(h);
    return (uint32_t)__bfloat16_as_ushort(h);
}

// ---------------------------------------------------------------------------
// k_weights: prepack B fragments (bf16 hi/lo) + tvec. 89 blocks x 256.
// ---------------------------------------------------------------------------
__global__ __launch_bounds__(256) void k_weights(const float* __restrict__ Wc,
                                                 const float* __restrict__ Wf,
                                                 const float* __restrict__ bf,
                                                 const float* __restrict__ Wk,
                                                 const float* __restrict__ Vw) {
    int T = blockIdx.x * 256 + threadIdx.x;
    if (T < 18432) {                       // val taps
        int tap = T / 2048;
        int rem = T & 2047;
        int kf = rem >> 8, nf = (rem >> 5) & 7, l = rem & 31;
        int c = nf * 8 + (l >> 2);
        int ks = kf * 16 + (l & 3) * 2;
        int fj[4] = {ks, ks + 1, ks + 8, ks + 9};
        uint32_t hb[4]; float lo[4];
#pragma unroll
        for (int j = 0; j < 4; j++)
            hb[j] = pkbf(Vw[(c * 128 + fj[j]) * 9 + tap], &lo[j]);
        g_Bt[tap][0][kf][nf][l][0] = hb[0] | (hb[1] << 16);
        g_Bt[tap][0][kf][nf][l][1] = hb[2] | (hb[3] << 16);
        uint32_t lb[4]; float dum;
#pragma unroll
        for (int j = 0; j < 4; j++) lb[j] = pkbf(lo[j], &dum);
        g_Bt[tap][1][kf][nf][l][0] = lb[0] | (lb[1] << 16);
        g_Bt[tap][1][kf][nf][l][1] = lb[2] | (lb[3] << 16);
    } else if (T < 22528) {                // center qt/key
        int T2 = T - 18432;
        int kf = T2 >> 9, nf = (T2 >> 5) & 15, l = T2 & 31;
        int n = nf * 8 + (l >> 2);
        int ks = kf * 16 + (l & 3) * 2;
        int fj[4] = {ks, ks + 1, ks + 8, ks + 9};
        uint32_t hb[4], lb[4]; float lo[4], dum;
#pragma unroll
        for (int j = 0; j < 4; j++) {
            float v;
            if (n < 64) {                  // qt: A[n][f] = Wc^T Wf
                v = 0.f;
                for (int d = 0; d < 64; d++) v = fmaf(Wc[d * 64 + n], Wf[d * 128 + fj[j]], v);
            } else {
                v = Wk[(n - 64) * 128 + fj[j]];
            }
            hb[j] = pkbf(v, &lo[j]);
            lb[j] = pkbf(lo[j], &dum);
        }
        g_Bq[0][kf][nf][l][0] = hb[0] | (hb[1] << 16);
        g_Bq[0][kf][nf][l][1] = hb[2] | (hb[3] << 16);
        g_Bq[1][kf][nf][l][0] = lb[0] | (lb[1] << 16);
        g_Bq[1][kf][nf][l][1] = lb[2] | (lb[3] << 16);
    } else if (T < 22592) {                // tvec
        int c = T - 22528;
        float t = 0.f;
        for (int d = 0; d < 64; d++) t = fmaf(Wc[d * 64 + c], bf[d], t);
        g_tvec[c] = t;
    }
}

// ---------------------------------------------------------------------------
// k_transpose: ms[B,128,64,64] -> g_m[split][padded slot][128f], swizzled.
// blocks 0..511: interior; blocks 512..519: zero the pad rings.
// ---------------------------------------------------------------------------
__global__ __launch_bounds__(256) void k_transpose(const float* __restrict__ ms) {
    int blk = blockIdx.x, tid = threadIdx.x;
    if (blk < 512) {
        __shared__ float sf[128 * 64];    // [f][x]
        int b = blk >> 6, y = blk & 63;
        for (int i = tid; i < 8192; i += 256)
            sf[i] = ms[((size_t)(b * 128 + (i >> 6)) * 64 + y) * 64 + (i & 63)];
        __syncthreads();
        for (int i = tid; i < 2048; i += 256) {
            int x = i & 63, ch = (i >> 6) & 15, s = i >> 10;
            int gr = b * IMG_SLOTS + (y + 1) * 66 + (x + 1);
            uint32_t out[4];
#pragma unroll
            for (int ff = 0; ff < 8; ff++) {
                float v = sf[(ch * 8 + ff) * 64 + x];
                __nv_bfloat16 hv = __float2bfloat16(v);
                float val = s ? (v - __bfloat162float(hv)) : v;
                uint32_t bits = (uint32_t)__bfloat16_as_ushort(__float2bfloat16(val));
                if (ff & 1) out[ff >> 1] = (bits << 16) | (out[ff >> 1] & 0xFFFF);
                else out[ff >> 1] = bits;
            }
            int swc = ch ^ (gr & 7);
            *(uint4*)&g_m[s][gr][swc * 8] = *(uint4*)out;
        }
    } else {
        // zero pad rings: 2 splits x 8 imgs x 260 slots x 16 chunks = 66560
        uint4 z = make_uint4(0, 0, 0, 0);
        int idx = (blk - 512) * 256 + tid;   // [0, 2048)
        for (int i = idx; i < 66560; i += 2048) {
            int ch = i & 15;
            int t = i >> 4;                  // [0, 4160)
            int slot = t % 260;
            int img = (t / 260) % 8;
            int s = t / 2080;
            int r;
            if (slot < 66) r = slot;                         // top pad row
            else if (slot < 132) r = 65 * 66 + (slot - 66);  // bottom pad row
            else {
                int j = slot - 132;
                r = (1 + (j >> 1)) * 66 + ((j & 1) ? 65 : 0);  // x pads
            }
            *(uint4*)&g_m[s][img * IMG_SLOTS + r][ch * 8] = z;
        }
    }
}

// ---------------------------------------------------------------------------
// k1: mma.sync implicit GEMM. 256 blocks x 512 threads, 128 pixels/block.
// A slab = 264 contiguous padded rows; taps offset by (dy-1)*66+(dx-1).
// ---------------------------------------------------------------------------
#define AS_OFF 0               // 264 rows * 256B = 67584
#define B0_OFF 67584
#define B1_OFF 100352
#define QS_OFF 133120
#define SV_OFF 0
#define SQ_OFF 33792
#define SK_OFF 67584
#define SB_OFF 198656
#define SMEM_K1 199424

__global__ __launch_bounds__(512, 1) void k1_mma(const float* __restrict__ Vb,
                                                 const float* __restrict__ bk) {
    extern __shared__ char smc[];
    uint32_t sb = smem_u32(smc);
    float* smf = (float*)smc;

    const int tid = threadIdx.x;
    const int lane = tid & 31, w = tid >> 5;
    const int mf = w & 7, nh = w >> 3;
    const int p0 = blockIdx.x * 128;
    const int bb = p0 >> 12, yy = (p0 >> 6) & 63;      // block covers rows yy, yy+1
    const int slabstart = bb * IMG_SLOTS + yy * 66;     // global padded row of slab[0]
    const int lr = (lane & 7) + (lane & 8);
    const int chi = lane >> 4;
    // pixel px = mf*16+lr -> slab-relative row 67 + px + (px>=64 ? 2 : 0)
    const int mfbase = 67 + mf * 16 + ((mf >= 4) ? 2 : 0);

    // stage biases (region untouched by async copies)
    if (tid < 64) {
        smf[SB_OFF / 4 + tid] = bk[tid];
        smf[SB_OFF / 4 + 64 + tid] = g_tvec[tid];
        smf[SB_OFF / 4 + 128 + tid] = Vb[tid];
    }

    // initial async loads: A(hi) slab + Q, then B tap0
    cpa16(sb + AS_OFF, &g_m[0][slabstart][0], 67584, tid);
    cpa16(sb + QS_OFF, &g_Bq[0][0][0][0][0], 65536, tid);
    CP_COMMIT();
    cpa16(sb + B0_OFF, &g_Bt[0][0][0][0][0][0], 32768, tid);
    CP_COMMIT();

    float aV[4][4], aQ[8][4];
#pragma unroll
    for (int j = 0; j < 4; j++)
#pragma unroll
        for (int u = 0; u < 4; u++) aV[j][u] = 0.f;
#pragma unroll
    for (int j = 0; j < 8; j++)
#pragma unroll
        for (int u = 0; u < 4; u++) aQ[j][u] = 0.f;

#pragma unroll 1
    for (int phase = 0; phase < 2; phase++) {
#pragma unroll 1
        for (int t = 0; t < 9; t++) {
            uint32_t bbuf = (t & 1) ? B1_OFF : B0_OFF;
            uint32_t nbuf = (t & 1) ? B0_OFF : B1_OFF;
            if (t < 8) {
                if (phase == 0)
                    cpa16(sb + nbuf, &g_Bt[t + 1][0][0][0][0][0], 32768, tid);
                else
                    cpa16(sb + nbuf, &g_Bt[t + 1][0][0][0][0][0], 16384, tid);
                CP_COMMIT();
                CP_WAIT1();
            } else {
                CP_WAIT0();
            }
            __syncthreads();

            int dy = t / 3, dx = t - dy * 3;
            int off = (dy - 1) * 66 + (dx - 1);
            int relrow = mfbase + off + lr;
            uint32_t abase = sb + AS_OFF + (uint32_t)relrow * 256;
            int rph = (slabstart + relrow) & 7;
            int passes = phase ? 1 : 2;
#pragma unroll 1
            for (int sB = 0; sB < passes; sB++) {
                uint32_t Bb = sb + bbuf + sB * 16384;
                uint32_t Qb = sb + QS_OFF + sB * 32768;   // g_Bq split stride
#pragma unroll
                for (int kf = 0; kf < 8; kf++) {
                    uint32_t a0, a1, a2, a3;
                    ldsm4(a0, a1, a2, a3, abase + ((((kf << 1) + chi) ^ rph) << 4));
#pragma unroll
                    for (int j = 0; j < 4; j++) {
                        int nf = nh * 4 + j;
                        uint32_t b0, b1;
                        lds64(b0, b1, Bb + ((kf * 8 + nf) * 32 + lane) * 8);
                        mma16816(aV[j], a0, a1, a2, a3, b0, b1);
                    }
                    if (t == 4) {
#pragma unroll
                        for (int j = 0; j < 8; j++) {
                            int qf = nh * 8 + j;
                            uint32_t b0, b1;
                            lds64(b0, b1, Qb + ((kf * 16 + qf) * 32 + lane) * 8);
                            mma16816(aQ[j], a0, a1, a2, a3, b0, b1);
                        }
                    }
                }
            }
            __syncthreads();
        }
        if (phase == 0) {
            cpa16(sb + AS_OFF, &g_m[1][slabstart][0], 67584, tid);   // A lo slab
            cpa16(sb + B0_OFF, &g_Bt[0][0][0][0][0][0], 16384, tid);
            CP_COMMIT();
        }
    }

    // ---- epilogue: stage D to smem (overlay), then coalesced writeout ----
    const int r0 = mf * 16 + (lane >> 2);
#pragma unroll
    for (int j = 0; j < 4; j++) {
        int c0 = (nh * 4 + j) * 8 + (lane & 3) * 2;
        smf[SV_OFF / 4 + c0 * 132 + r0] = aV[j][0];
        smf[SV_OFF / 4 + (c0 + 1) * 132 + r0] = aV[j][1];
        smf[SV_OFF / 4 + c0 * 132 + r0 + 8] = aV[j][2];
        smf[SV_OFF / 4 + (c0 + 1) * 132 + r0 + 8] = aV[j][3];
    }
#pragma unroll
    for (int j = 0; j < 8; j++) {
        int nq = (nh * 8 + j) * 8 + (lane & 3) * 2;    // 0..63 qt | 64..127 key
        int base = (nq < 64) ? SQ_OFF / 4 : SK_OFF / 4;
        int cc = nq & 63;
        smf[base + cc * 132 + r0] = aQ[j][0];
        smf[base + (cc + 1) * 132 + r0] = aQ[j][1];
        smf[base + cc * 132 + r0 + 8] = aQ[j][2];
        smf[base + (cc + 1) * 132 + r0 + 8] = aQ[j][3];
    }
    __syncthreads();

#pragma unroll
    for (int rep = 0; rep < 16; rep++) {
        int idx = rep * 512 + tid;
        int c = idx >> 7, px = idx & 127;
        int p = p0 + px;
        int gi = ((p >> 12) * 64 + c) * 4096 + (p & 4095);
        g_Val[gi] = smf[SV_OFF / 4 + c * 132 + px] + smf[SB_OFF / 4 + 128 + c];
        g_Qt[gi] = smf[SQ_OFF / 4 + c * 132 + px] + smf[SB_OFF / 4 + 64 + c];
    }
    {
        int px = tid >> 2, q = tid & 3;
        float s = 0.f;
#pragma unroll 4
        for (int cc = q * 16; cc < q * 16 + 16; cc++) {
            float key = smf[SK_OFF / 4 + cc * 132 + px] + smf[SB_OFF / 4 + cc];
            float qt = smf[SQ_OFF / 4 + cc * 132 + px] + smf[SB_OFF / 4 + 64 + cc];
            s = fmaf(key, qt, s);
        }
        s += __shfl_down_sync(0xffffffffu, s, 1);
        s += __shfl_down_sync(0xffffffffu, s, 2);
        if (q == 0) {
            int p = p0 + px;
            g_Lm[(p >> 12) * 4096 + (p & 4095)] = s;
        }
    }
}

// ---------------------------------------------------------------------------
// k2: high-res attention (unchanged from the passing version)
// ---------------------------------------------------------------------------
__global__ __launch_bounds__(256) void k2_highres(const float* __restrict__ ctx,
                                                  float* __restrict__ out) {
    int idx = blockIdx.x * 256 + threadIdx.x;
    int b = idx >> 13;
    int rem = idx & 8191;
    int hr = rem >> 6;
    int x = rem & 63;
    int y = hr >> 1;

    const float* qt = g_Qt + ((b * 64) * 64 + y) * 64 + x;
    const float2* cp2 = (const float2*)(ctx + (size_t)b * 3 * 64 * 16384 + hr * 128) + x;

    float2 l0 = make_float2(0.f, 0.f), l1 = l0, l2 = l0;
#pragma unroll 4
    for (int c = 0; c < 64; c++) {
        float q = qt[c * 4096];
        float2 a = cp2[c * 8192];
        float2 d = cp2[(64 + c) * 8192];
        float2 e = cp2[(128 + c) * 8192];
        l0.x = fmaf(a.x, q, l0.x); l0.y = fmaf(a.y, q, l0.y);
        l1.x = fmaf(d.x, q, l1.x); l1.y = fmaf(d.y, q, l1.y);
        l2.x = fmaf(e.x, q, l2.x); l2.y = fmaf(e.y, q, l2.y);
    }
    float l3 = g_Lm[(b * 64 + y) * 64 + x];

    float2 w0, w1, w2, w3;
    {
        float mx = fmaxf(fmaxf(l0.x, l1.x), fmaxf(l2.x, l3));
        float e0 = __expf(l0.x - mx), e1 = __expf(l1.x - mx);
        float e2 = __expf(l2.x - mx), e3 = __expf(l3 - mx);
        float inv = 1.f / (e0 + e1 + e2 + e3);
        w0.x = e0 * inv; w1.x = e1 * inv; w2.x = e2 * inv; w3.x = e3 * inv;
    }
    {
        float mx = fmaxf(fmaxf(l0.y, l1.y), fmaxf(l2.y, l3));
        float e0 = __expf(l0.y - mx), e1 = __expf(l1.y - mx);
        float e2 = __expf(l2.y - mx), e3 = __expf(l3 - mx);
        float inv = 1.f / (e0 + e1 + e2 + e3);
        w0.y = e0 * inv; w1.y = e1 * inv; w2.y = e2 * inv; w3.y = e3 * inv;
    }

    const float* vp = g_Val + ((b * 64) * 64 + y) * 64 + x;
    float2* op = (float2*)(out + (size_t)b * 64 * 16384 + hr * 128) + x;
#pragma unroll 4
    for (int c = 0; c < 64; c++) {
        float v = vp[c * 4096];
        float2 a = cp2[c * 8192];
        float2 d = cp2[(64 + c) * 8192];
        float2 e = cp2[(128 + c) * 8192];
        float2 o;
        o.x = w3.x * v; o.y = w3.y * v;
        o.x = fmaf(w0.x, a.x, o.x); o.y = fmaf(w0.y, a.y, o.y);
        o.x = fmaf(w1.x, d.x, o.x); o.y = fmaf(w1.y, d.y, o.y);
        o.x = fmaf(w2.x, e.x, o.x); o.y = fmaf(w2.y, e.y, o.y);
        op[c * 8192] = o;
    }
}

// ---------------------------------------------------------------------------
extern "C" void kernel_launch(void* const* d_in, const int* in_sizes, int n_in,
                              void* d_out, int out_size) {
    (void)in_sizes; (void)n_in; (void)out_size;
    const float* contexts = (const float*)d_in[0];
    const float* mainstream = (const float*)d_in[1];
    const float* Wc = (const float*)d_in[2];
    // d_in[3] = bc : cancels in softmax, unused
    const float* Wf = (const float*)d_in[4];
    const float* bf = (const float*)d_in[5];
    const float* Wk = (const float*)d_in[6];
    const float* bk = (const float*)d_in[7];
    const float* Vw = (const float*)d_in[8];
    const float* Vb = (const float*)d_in[9];
    float* out = (float*)d_out;

    cudaFuncSetAttribute(k1_mma, cudaFuncAttributeMaxDynamicSharedMemorySize, SMEM_K1);

    k_weights<<<89, 256>>>(Wc, Wf, bf, Wk, Vw);
    k_transpose<<<520, 256>>>(mainstream);
    k1_mma<<<256, 512, SMEM_K1>>>(Vb, bk);
    k2_highres<<<256, 256>>>(contexts, out);
}

// round 11
// speedup vs baseline: 3.6592x; 1.2600x over previous
#include <cuda_runtime.h>
#include <cuda_bf16.h>
#include <cstdint>
#include <math.h>

// padded image: 66x66 slots per image, pixel (y,x) at slot (y+1)*66+(x+1)
#define IMG_SLOTS 4356
#define NROW (8 * IMG_SLOTS)   // 34848 padded pixel rows

// ---------------- device scratch (no allocation allowed) ----------------
__device__ float g_tvec[64];
__device__ float g_Qt[8 * 64 * 64 * 64];
__device__ float g_Val[8 * 64 * 64 * 64];
__device__ float g_Lm[8 * 64 * 64];
// transposed mainstream, bf16 hi/lo split, XOR-swizzled rows, per-image pad ring
__device__ __nv_bfloat16 g_m[2][NROW][128];
// B weights prepacked in mma-fragment layout:
// taps: [tap][split][kf][nf(8)][lane(32)][2] u32  (val channels only)
__device__ uint32_t g_Bt[9][2][8][8][32][2];
// center qt/key: [split][kf][nf(16)][lane][2]  (n = 64+qt / 128+key)
__device__ uint32_t g_Bq[2][8][16][32][2];

// ---------------- PTX helpers (ALL baseline sm_80-class features) -------
__device__ __forceinline__ uint32_t smem_u32(const void* p) {
    uint32_t a;
    asm("{ .reg .u64 t; cvta.to.shared.u64 t, %1; cvt.u32.u64 %0, t; }" : "=r"(a) : "l"(p));
    return a;
}
__device__ __forceinline__ void cpa16(uint32_t dst, const void* src, int bytes, int tid) {
    const char* s = (const char*)src;
    for (int o = tid * 16; o < bytes; o += 512 * 16)
        asm volatile("cp.async.cg.shared.global [%0], [%1], 16;" :: "r"(dst + o), "l"(s + o));
}
#define CP_COMMIT() asm volatile("cp.async.commit_group;" ::: "memory")
#define CP_WAIT1()  asm volatile("cp.async.wait_group 1;" ::: "memory")
#define CP_WAIT0()  asm volatile("cp.async.wait_group 0;" ::: "memory")

__device__ __forceinline__ void ldsm4(uint32_t& a0, uint32_t& a1, uint32_t& a2, uint32_t& a3,
                                      uint32_t addr) {
    asm volatile("ldmatrix.sync.aligned.m8n8.x4.shared.b16 {%0,%1,%2,%3}, [%4];"
                 : "=r"(a0), "=r"(a1), "=r"(a2), "=r"(a3) : "r"(addr));
}
__device__ __forceinline__ void lds64(uint32_t& b0, uint32_t& b1, uint32_t addr) {
    asm volatile("ld.shared.v2.u32 {%0,%1}, [%2];" : "=r"(b0), "=r"(b1) : "r"(addr));
}
__device__ __forceinline__ void mma16816(float* d, uint32_t a0, uint32_t a1, uint32_t a2,
                                         uint32_t a3, uint32_t b0, uint32_t b1) {
    asm volatile(
        "mma.sync.aligned.m16n8k16.row.col.f32.bf16.bf16.f32 "
        "{%0,%1,%2,%3}, {%4,%5,%6,%7}, {%8,%9}, {%0,%1,%2,%3};"
        : "+f"(d[0]), "+f"(d[1]), "+f"(d[2]), "+f"(d[3])
        : "r"(a0), "r"(a1), "r"(a2), "r"(a3), "r"(b0), "r"(b1));
}

__device__ __forceinline__ uint32_t pkbf(float v, float* res) {
    __nv_bfloat16 h = __float2bfloat16(v);
    *res = v - __bfloat162float(h);
    return (uint32_t)__bfloat16_as_ushort(h);
}

// ---------------------------------------------------------------------------
// k_weights: prepack B fragments (bf16 hi/lo) + tvec. 89 blocks x 256.
// ---------------------------------------------------------------------------
__global__ __launch_bounds__(256) void k_weights(const float* __restrict__ Wc,
                                                 const float* __restrict__ Wf,
                                                 const float* __restrict__ bf,
                                                 const float* __restrict__ Wk,
                                                 const float* __restrict__ Vw) {
    int T = blockIdx.x * 256 + threadIdx.x;
    if (T < 18432) {                       // val taps
        int tap = T / 2048;
        int rem = T & 2047;
        int kf = rem >> 8, nf = (rem >> 5) & 7, l = rem & 31;
        int c = nf * 8 + (l >> 2);
        int ks = kf * 16 + (l & 3) * 2;
        int fj[4] = {ks, ks + 1, ks + 8, ks + 9};
        uint32_t hb[4]; float lo[4];
#pragma unroll
        for (int j = 0; j < 4; j++)
            hb[j] = pkbf(Vw[(c * 128 + fj[j]) * 9 + tap], &lo[j]);
        g_Bt[tap][0][kf][nf][l][0] = hb[0] | (hb[1] << 16);
        g_Bt[tap][0][kf][nf][l][1] = hb[2] | (hb[3] << 16);
        uint32_t lb[4]; float dum;
#pragma unroll
        for (int j = 0; j < 4; j++) lb[j] = pkbf(lo[j], &dum);
        g_Bt[tap][1][kf][nf][l][0] = lb[0] | (lb[1] << 16);
        g_Bt[tap][1][kf][nf][l][1] = lb[2] | (lb[3] << 16);
    } else if (T < 22528) {                // center qt/key
        int T2 = T - 18432;
        int kf = T2 >> 9, nf = (T2 >> 5) & 15, l = T2 & 31;
        int n = nf * 8 + (l >> 2);
        int ks = kf * 16 + (l & 3) * 2;
        int fj[4] = {ks, ks + 1, ks + 8, ks + 9};
        uint32_t hb[4], lb[4]; float lo[4], dum;
#pragma unroll
        for (int j = 0; j < 4; j++) {
            float v;
            if (n < 64) {                  // qt: A[n][f] = Wc^T Wf
                v = 0.f;
                for (int d = 0; d < 64; d++) v = fmaf(Wc[d * 64 + n], Wf[d * 128 + fj[j]], v);
            } else {
                v = Wk[(n - 64) * 128 + fj[j]];
            }
            hb[j] = pkbf(v, &lo[j]);
            lb[j] = pkbf(lo[j], &dum);
        }
        g_Bq[0][kf][nf][l][0] = hb[0] | (hb[1] << 16);
        g_Bq[0][kf][nf][l][1] = hb[2] | (hb[3] << 16);
        g_Bq[1][kf][nf][l][0] = lb[0] | (lb[1] << 16);
        g_Bq[1][kf][nf][l][1] = lb[2] | (lb[3] << 16);
    } else if (T < 22592) {                // tvec
        int c = T - 22528;
        float t = 0.f;
        for (int d = 0; d < 64; d++) t = fmaf(Wc[d * 64 + c], bf[d], t);
        g_tvec[c] = t;
    }
}

// ---------------------------------------------------------------------------
// k_transpose: ms[B,128,64,64] -> g_m[split][padded slot][128f], swizzled.
// blocks 0..511: interior; blocks 512..519: zero the pad rings.
// ---------------------------------------------------------------------------
__global__ __launch_bounds__(256) void k_transpose(const float* __restrict__ ms) {
    int blk = blockIdx.x, tid = threadIdx.x;
    if (blk < 512) {
        __shared__ float sf[128 * 64];    // [f][x]
        int b = blk >> 6, y = blk & 63;
        for (int i = tid; i < 8192; i += 256)
            sf[i] = ms[((size_t)(b * 128 + (i >> 6)) * 64 + y) * 64 + (i & 63)];
        __syncthreads();
        for (int i = tid; i < 2048; i += 256) {
            int x = i & 63, ch = (i >> 6) & 15, s = i >> 10;
            int gr = b * IMG_SLOTS + (y + 1) * 66 + (x + 1);
            uint32_t out[4];
#pragma unroll
            for (int ff = 0; ff < 8; ff++) {
                float v = sf[(ch * 8 + ff) * 64 + x];
                __nv_bfloat16 hv = __float2bfloat16(v);
                float val = s ? (v - __bfloat162float(hv)) : v;
                uint32_t bits = (uint32_t)__bfloat16_as_ushort(__float2bfloat16(val));
                if (ff & 1) out[ff >> 1] = (bits << 16) | (out[ff >> 1] & 0xFFFF);
                else out[ff >> 1] = bits;
            }
            int swc = ch ^ (gr & 7);
            *(uint4*)&g_m[s][gr][swc * 8] = *(uint4*)out;
        }
    } else {
        // zero pad rings: 2 splits x 8 imgs x 260 slots x 16 chunks = 66560
        uint4 z = make_uint4(0, 0, 0, 0);
        int idx = (blk - 512) * 256 + tid;   // [0, 2048)
        for (int i = idx; i < 66560; i += 2048) {
            int ch = i & 15;
            int t = i >> 4;                  // [0, 4160)
            int slot = t % 260;
            int img = (t / 260) % 8;
            int s = t / 2080;
            int r;
            if (slot < 66) r = slot;                         // top pad row
            else if (slot < 132) r = 65 * 66 + (slot - 66);  // bottom pad row
            else {
                int j = slot - 132;
                r = (1 + (j >> 1)) * 66 + ((j & 1) ? 65 : 0);  // x pads
            }
            *(uint4*)&g_m[s][img * IMG_SLOTS + r][ch * 8] = z;
        }
    }
}

// ---------------------------------------------------------------------------
// k1: mma.sync implicit GEMM. 256 blocks x 512 threads, 128 pixels/block.
// A slab = 264 contiguous padded rows; taps offset by (dy-1)*66+(dx-1).
// ---------------------------------------------------------------------------
#define AS_OFF 0               // 264 rows * 256B = 67584
#define B0_OFF 67584
#define B1_OFF 100352
#define QS_OFF 133120
#define SV_OFF 0
#define SQ_OFF 33792
#define SK_OFF 67584
#define SB_OFF 198656
#define SMEM_K1 199424

__global__ __launch_bounds__(512, 1) void k1_mma(const float* __restrict__ Vb,
                                                 const float* __restrict__ bk) {
    extern __shared__ char smc[];
    uint32_t sb = smem_u32(smc);
    float* smf = (float*)smc;

    const int tid = threadIdx.x;
    const int lane = tid & 31, w = tid >> 5;
    const int mf = w & 7, nh = w >> 3;
    const int p0 = blockIdx.x * 128;
    const int bb = p0 >> 12, yy = (p0 >> 6) & 63;      // block covers rows yy, yy+1
    const int slabstart = bb * IMG_SLOTS + yy * 66;     // global padded row of slab[0]
    const int lr = (lane & 7) + (lane & 8);
    const int chi = lane >> 4;
    // pixel px = mf*16+lr -> slab-relative row 67 + px + (px>=64 ? 2 : 0)
    const int mfbase = 67 + mf * 16 + ((mf >= 4) ? 2 : 0);

    // stage biases (region untouched by async copies)
    if (tid < 64) {
        smf[SB_OFF / 4 + tid] = bk[tid];
        smf[SB_OFF / 4 + 64 + tid] = g_tvec[tid];
        smf[SB_OFF / 4 + 128 + tid] = Vb[tid];
    }

    // initial async loads: A(hi) slab + Q, then B tap0
    cpa16(sb + AS_OFF, &g_m[0][slabstart][0], 67584, tid);
    cpa16(sb + QS_OFF, &g_Bq[0][0][0][0][0], 65536, tid);
    CP_COMMIT();
    cpa16(sb + B0_OFF, &g_Bt[0][0][0][0][0][0], 32768, tid);
    CP_COMMIT();

    float aV[4][4], aQ[8][4];
#pragma unroll
    for (int j = 0; j < 4; j++)
#pragma unroll
        for (int u = 0; u < 4; u++) aV[j][u] = 0.f;
#pragma unroll
    for (int j = 0; j < 8; j++)
#pragma unroll
        for (int u = 0; u < 4; u++) aQ[j][u] = 0.f;

#pragma unroll 1
    for (int phase = 0; phase < 2; phase++) {
#pragma unroll 1
        for (int t = 0; t < 9; t++) {
            uint32_t bbuf = (t & 1) ? B1_OFF : B0_OFF;
            uint32_t nbuf = (t & 1) ? B0_OFF : B1_OFF;
            if (t < 8) {
                if (phase == 0)
                    cpa16(sb + nbuf, &g_Bt[t + 1][0][0][0][0][0], 32768, tid);
                else
                    cpa16(sb + nbuf, &g_Bt[t + 1][0][0][0][0][0], 16384, tid);
                CP_COMMIT();
                CP_WAIT1();
            } else {
                CP_WAIT0();
            }
            __syncthreads();

            int dy = t / 3, dx = t - dy * 3;
            int off = (dy - 1) * 66 + (dx - 1);
            int relrow = mfbase + off + lr;
            uint32_t abase = sb + AS_OFF + (uint32_t)relrow * 256;
            int rph = (slabstart + relrow) & 7;
            int passes = phase ? 1 : 2;
#pragma unroll 1
            for (int sB = 0; sB < passes; sB++) {
                uint32_t Bb = sb + bbuf + sB * 16384;
                uint32_t Qb = sb + QS_OFF + sB * 32768;   // g_Bq split stride
#pragma unroll
                for (int kf = 0; kf < 8; kf++) {
                    uint32_t a0, a1, a2, a3;
                    ldsm4(a0, a1, a2, a3, abase + ((((kf << 1) + chi) ^ rph) << 4));
#pragma unroll
                    for (int j = 0; j < 4; j++) {
                        int nf = nh * 4 + j;
                        uint32_t b0, b1;
                        lds64(b0, b1, Bb + ((kf * 8 + nf) * 32 + lane) * 8);
                        mma16816(aV[j], a0, a1, a2, a3, b0, b1);
                    }
                    if (t == 4) {
#pragma unroll
                        for (int j = 0; j < 8; j++) {
                            int qf = nh * 8 + j;
                            uint32_t b0, b1;
                            lds64(b0, b1, Qb + ((kf * 16 + qf) * 32 + lane) * 8);
                            mma16816(aQ[j], a0, a1, a2, a3, b0, b1);
                        }
                    }
                }
            }
            __syncthreads();
        }
        if (phase == 0) {
            cpa16(sb + AS_OFF, &g_m[1][slabstart][0], 67584, tid);   // A lo slab
            cpa16(sb + B0_OFF, &g_Bt[0][0][0][0][0][0], 16384, tid);
            CP_COMMIT();
        }
    }

    // ---- epilogue: stage D to smem (overlay), then coalesced writeout ----
    const int r0 = mf * 16 + (lane >> 2);
#pragma unroll
    for (int j = 0; j < 4; j++) {
        int c0 = (nh * 4 + j) * 8 + (lane & 3) * 2;
        smf[SV_OFF / 4 + c0 * 132 + r0] = aV[j][0];
        smf[SV_OFF / 4 + (c0 + 1) * 132 + r0] = aV[j][1];
        smf[SV_OFF / 4 + c0 * 132 + r0 + 8] = aV[j][2];
        smf[SV_OFF / 4 + (c0 + 1) * 132 + r0 + 8] = aV[j][3];
    }
#pragma unroll
    for (int j = 0; j < 8; j++) {
        int nq = (nh * 8 + j) * 8 + (lane & 3) * 2;    // 0..63 qt | 64..127 key
        int base = (nq < 64) ? SQ_OFF / 4 : SK_OFF / 4;
        int cc = nq & 63;
        smf[base + cc * 132 + r0] = aQ[j][0];
        smf[base + (cc + 1) * 132 + r0] = aQ[j][1];
        smf[base + cc * 132 + r0 + 8] = aQ[j][2];
        smf[base + (cc + 1) * 132 + r0 + 8] = aQ[j][3];
    }
    __syncthreads();

#pragma unroll
    for (int rep = 0; rep < 16; rep++) {
        int idx = rep * 512 + tid;
        int c = idx >> 7, px = idx & 127;
        int p = p0 + px;
        int gi = ((p >> 12) * 64 + c) * 4096 + (p & 4095);
        g_Val[gi] = smf[SV_OFF / 4 + c * 132 + px] + smf[SB_OFF / 4 + 128 + c];
        g_Qt[gi] = smf[SQ_OFF / 4 + c * 132 + px] + smf[SB_OFF / 4 + 64 + c];
    }
    {
        int px = tid >> 2, q = tid & 3;
        float s = 0.f;
#pragma unroll 4
        for (int cc = q * 16; cc < q * 16 + 16; cc++) {
            float key = smf[SK_OFF / 4 + cc * 132 + px] + smf[SB_OFF / 4 + cc];
            float qt = smf[SQ_OFF / 4 + cc * 132 + px] + smf[SB_OFF / 4 + 64 + cc];
            s = fmaf(key, qt, s);
        }
        s += __shfl_down_sync(0xffffffffu, s, 1);
        s += __shfl_down_sync(0xffffffffu, s, 2);
        if (q == 0) {
            int p = p0 + px;
            g_Lm[(p >> 12) * 4096 + (p & 4095)] = s;
        }
    }
}

// ---------------------------------------------------------------------------
// k2 v2: high-res attention, c-loop split 4 ways for occupancy.
// 1024 blocks x 256 thr; thread = (pixel-pair, quarter q). Each q handles
// 16 channels; logits butterfly-reduced across the 4 lanes of a pair.
// ---------------------------------------------------------------------------
__global__ __launch_bounds__(256) void k2_highres(const float* __restrict__ ctx,
                                                  float* __restrict__ out) {
    int idx = blockIdx.x * 256 + threadIdx.x;    // 262144 threads
    int q = idx & 3;
    int pp = idx >> 2;                           // pixel-pair id [0, 65536)
    int b = pp >> 13;
    int rem = pp & 8191;
    int hr = rem >> 6;
    int x = rem & 63;
    int y = hr >> 1;
    int c0 = q * 16;

    const float* qt = g_Qt + ((b * 64 + c0) * 64 + y) * 64 + x;
    const float2* cp2 = (const float2*)(ctx + (size_t)b * 3 * 64 * 16384 + hr * 128)
                        + x + (size_t)c0 * 8192;

    float2 l0 = make_float2(0.f, 0.f), l1 = l0, l2 = l0;
#pragma unroll 4
    for (int c = 0; c < 16; c++) {
        float qv = qt[c * 4096];
        float2 a = cp2[c * 8192];
        float2 d = cp2[(64 + c) * 8192];
        float2 e = cp2[(128 + c) * 8192];
        l0.x = fmaf(a.x, qv, l0.x); l0.y = fmaf(a.y, qv, l0.y);
        l1.x = fmaf(d.x, qv, l1.x); l1.y = fmaf(d.y, qv, l1.y);
        l2.x = fmaf(e.x, qv, l2.x); l2.y = fmaf(e.y, qv, l2.y);
    }
    // butterfly over the 4 lanes sharing this pixel-pair (bits 0-1 of lane)
#pragma unroll
    for (int m = 1; m <= 2; m <<= 1) {
        l0.x += __shfl_xor_sync(0xffffffffu, l0.x, m);
        l0.y += __shfl_xor_sync(0xffffffffu, l0.y, m);
        l1.x += __shfl_xor_sync(0xffffffffu, l1.x, m);
        l1.y += __shfl_xor_sync(0xffffffffu, l1.y, m);
        l2.x += __shfl_xor_sync(0xffffffffu, l2.x, m);
        l2.y += __shfl_xor_sync(0xffffffffu, l2.y, m);
    }
    float l3 = g_Lm[(b * 64 + y) * 64 + x];

    float2 w0, w1, w2, w3;
    {
        float mx = fmaxf(fmaxf(l0.x, l1.x), fmaxf(l2.x, l3));
        float e0 = __expf(l0.x - mx), e1 = __expf(l1.x - mx);
        float e2 = __expf(l2.x - mx), e3 = __expf(l3 - mx);
        float inv = 1.f / (e0 + e1 + e2 + e3);
        w0.x = e0 * inv; w1.x = e1 * inv; w2.x = e2 * inv; w3.x = e3 * inv;
    }
    {
        float mx = fmaxf(fmaxf(l0.y, l1.y), fmaxf(l2.y, l3));
        float e0 = __expf(l0.y - mx), e1 = __expf(l1.y - mx);
        float e2 = __expf(l2.y - mx), e3 = __expf(l3 - mx);
        float inv = 1.f / (e0 + e1 + e2 + e3);
        w0.y = e0 * inv; w1.y = e1 * inv; w2.y = e2 * inv; w3.y = e3 * inv;
    }

    const float* vp = g_Val + ((b * 64 + c0) * 64 + y) * 64 + x;
    float2* op = (float2*)(out + (size_t)(b * 64 + c0) * 16384 + hr * 128) + x;
#pragma unroll 4
    for (int c = 0; c < 16; c++) {
        float v = vp[c * 4096];
        float2 a = cp2[c * 8192];
        float2 d = cp2[(64 + c) * 8192];
        float2 e = cp2[(128 + c) * 8192];
        float2 o;
        o.x = w3.x * v; o.y = w3.y * v;
        o.x = fmaf(w0.x, a.x, o.x); o.y = fmaf(w0.y, a.y, o.y);
        o.x = fmaf(w1.x, d.x, o.x); o.y = fmaf(w1.y, d.y, o.y);
        o.x = fmaf(w2.x, e.x, o.x); o.y = fmaf(w2.y, e.y, o.y);
        op[c * 8192] = o;
    }
}

// ---------------------------------------------------------------------------
extern "C" void kernel_launch(void* const* d_in, const int* in_sizes, int n_in,
                              void* d_out, int out_size) {
    (void)in_sizes; (void)n_in; (void)out_size;
    const float* contexts = (const float*)d_in[0];
    const float* mainstream = (const float*)d_in[1];
    const float* Wc = (const float*)d_in[2];
    // d_in[3] = bc : cancels in softmax, unused
    const float* Wf = (const float*)d_in[4];
    const float* bf = (const float*)d_in[5];
    const float* Wk = (const float*)d_in[6];
    const float* bk = (const float*)d_in[7];
    const float* Vw = (const float*)d_in[8];
    const float* Vb = (const float*)d_in[9];
    float* out = (float*)d_out;

    cudaFuncSetAttribute(k1_mma, cudaFuncAttributeMaxDynamicSharedMemorySize, SMEM_K1);

    k_weights<<<89, 256>>>(Wc, Wf, bf, Wk, Vw);
    k_transpose<<<520, 256>>>(mainstream);
    k1_mma<<<256, 512, SMEM_K1>>>(Vb, bk);
    k2_highres<<<1024, 256>>>(contexts, out);
}